// round 1
// baseline (speedup 1.0000x reference)
#include <cuda_runtime.h>
#include <cstdint>
#include <cstdio>

// ---------------------------------------------------------------------------
// NeRF fused MLP, fp32 baseline using packed fma.rn.f32x2 (Blackwell).
// One CTA processes TM=128 samples through all layers; activations in SMEM,
// weights streamed through SMEM in K-chunks with cp.async double buffering.
// ---------------------------------------------------------------------------

#define TM        128          // samples per CTA
#define NTHREADS  512          // 16 warps
#define HS        272          // h row stride (floats), fits 268 + pad, even
#define WS        260          // weight chunk col stride (floats), even
#define KC        16           // K-chunk depth

#define SMEM_FLOATS (TM*HS + 2*KC*WS + 260 + 256)
#define SMEM_BYTES  (SMEM_FLOATS * 4)

struct Params {
    const float* x;
    const float* d;
    const float* W[9];
    const float* b[9];
    const float* Wc0; const float* bc0;
    const float* Wc1; const float* bc1;
};

// ---- packed fp32x2 helpers -------------------------------------------------
__device__ __forceinline__ unsigned long long splat2(float v) {
    unsigned long long r;
    asm("mov.b64 %0, {%1, %2};" : "=l"(r) : "f"(v), "f"(v));
    return r;
}
__device__ __forceinline__ unsigned long long ffma2(unsigned long long a,
                                                    unsigned long long b,
                                                    unsigned long long c) {
    unsigned long long d;
    asm("fma.rn.f32x2 %0, %1, %2, %3;" : "=l"(d) : "l"(a), "l"(b), "l"(c));
    return d;
}
__device__ __forceinline__ float2 unpack2(unsigned long long v) {
    float2 f;
    asm("mov.b64 {%0, %1}, %2;" : "=f"(f.x), "=f"(f.y) : "l"(v));
    return f;
}

// ---- cp.async helpers ------------------------------------------------------
__device__ __forceinline__ void cp_async4(void* dst, const void* src) {
    unsigned sa = (unsigned)__cvta_generic_to_shared(dst);
    asm volatile("cp.async.ca.shared.global [%0], [%1], 4;" :: "r"(sa), "l"(src));
}
__device__ __forceinline__ void cp_commit() { asm volatile("cp.async.commit_group;"); }
__device__ __forceinline__ void cp_wait0()  { asm volatile("cp.async.wait_group 0;"); }
__device__ __forceinline__ void cp_wait1()  { asm volatile("cp.async.wait_group 1;"); }

// Stage one K-chunk of W [kchunk x Nw] into smem (col stride WS).
// L8: global col 0 (sigma weights) is redirected to wcol0[], cols 1..256 are
// shifted left by one so the main GEMM sees even, float2-aligned columns.
template<bool L8>
__device__ __forceinline__ void stage_chunk(const float* __restrict__ Wg,
                                            int K, int Nw, int c,
                                            float* wdst, float* wcol0, int tid) {
    int kbase  = c * KC;
    int kchunk = min(KC, K - kbase);
    int cnt    = kchunk * Nw;
    const float* src = Wg + (size_t)kbase * Nw;
    for (int idx = tid; idx < cnt; idx += NTHREADS) {
        int rr = idx / Nw;
        int cc = idx - rr * Nw;
        if (L8) {
            if (cc == 0) cp_async4(&wcol0[kbase + rr], src + idx);
            else         cp_async4(&wdst[rr * WS + (cc - 1)], src + idx);
        } else {
            cp_async4(&wdst[rr * WS + cc], src + idx);
        }
    }
}

// One dense layer: h[TM x K] @ W[K x Nw] + b, ReLU, result back into h.
// Thread tile: 8 rows (ty*8..+7) x 2*NP cols (pairs at 2*(tx+32*j)).
// For L8 the main GEMM produces fx (global cols 1..256 -> h cols 0..255) and
// a side pass produces sigma (global col 0) written straight to out[].
template<int NP, bool L8>
__device__ __forceinline__ void dense_layer(float* h, float* wbuf, float* bias_s,
                                            float* wcol0,
                                            const float* __restrict__ Wg,
                                            const float* __restrict__ bg,
                                            int K, int Nw,
                                            int tid, int tx, int ty,
                                            float* out, int s0, int ns) {
    const int Ncols = NP * 64;
    for (int j = tid; j < Ncols; j += NTHREADS) bias_s[j] = bg[j + (L8 ? 1 : 0)];

    unsigned long long acc[8][NP];
#pragma unroll
    for (int i = 0; i < 8; i++)
#pragma unroll
        for (int j = 0; j < NP; j++) acc[i][j] = 0ull;

    int nchunks = (K + KC - 1) / KC;
    stage_chunk<L8>(Wg, K, Nw, 0, wbuf, wcol0, tid);
    cp_commit();
    int buf = 0;
    for (int c = 0; c < nchunks; c++) {
        if (c + 1 < nchunks) {
            stage_chunk<L8>(Wg, K, Nw, c + 1, wbuf + (buf ^ 1) * (KC * WS), wcol0, tid);
            cp_commit();
            cp_wait1();
        } else {
            cp_wait0();
        }
        __syncthreads();   // chunk c visible to all; buffer buf^1 free for staging done above

        int kbase  = c * KC;
        int kchunk = min(KC, K - kbase);        // always even (16/14/12)
        const float* wb = wbuf + buf * (KC * WS);
        for (int kk = 0; kk < kchunk; kk += 2) {
            unsigned long long wv0[NP], wv1[NP];
#pragma unroll
            for (int j = 0; j < NP; j++) {
                int cc = 2 * (tx + 32 * j);
                wv0[j] = *(const unsigned long long*)&wb[kk * WS + cc];
                wv1[j] = *(const unsigned long long*)&wb[(kk + 1) * WS + cc];
            }
#pragma unroll
            for (int i = 0; i < 8; i++) {
                float2 hp = *(const float2*)&h[(ty * 8 + i) * HS + kbase + kk];
                unsigned long long ha = splat2(hp.x);
                unsigned long long hb = splat2(hp.y);
#pragma unroll
                for (int j = 0; j < NP; j++) {
                    acc[i][j] = ffma2(ha, wv0[j], acc[i][j]);
                    acc[i][j] = ffma2(hb, wv1[j], acc[i][j]);
                }
            }
        }
        __syncthreads();   // all threads done reading buffer buf before it is restaged
        buf ^= 1;
    }

    if (L8) {
        // sigma = relu(h . wcol0 + b[0]); h still holds layer-8 input here.
        int r = tid >> 2, q = tid & 3;
        float s = 0.f;
#pragma unroll 4
        for (int k = q * 64; k < q * 64 + 64; ++k) s += h[r * HS + k] * wcol0[k];
        s += __shfl_xor_sync(0xffffffffu, s, 1);
        s += __shfl_xor_sync(0xffffffffu, s, 2);
        if (q == 0 && (s0 + r) < ns) out[s0 + r] = fmaxf(s + bg[0], 0.f);
        __syncthreads();   // sigma readers done before h is overwritten with fx
    }

    // writeback relu(acc + bias) into h (aligned float2 stores, conflict-free)
#pragma unroll
    for (int i = 0; i < 8; i++) {
        int r = ty * 8 + i;
#pragma unroll
        for (int j = 0; j < NP; j++) {
            int cc = 2 * (tx + 32 * j);
            float2 a  = unpack2(acc[i][j]);
            float2 b2 = *(const float2*)&bias_s[cc];
            float2 o;
            o.x = fmaxf(a.x + b2.x, 0.f);
            o.y = fmaxf(a.y + b2.y, 0.f);
            *(float2*)&h[r * HS + cc] = o;
        }
    }
    __syncthreads();
}

__global__ void __launch_bounds__(NTHREADS, 1)
nerf_fused_kernel(Params p, float* __restrict__ out, int ns) {
    extern __shared__ float smem[];
    float* h      = smem;                       // TM * HS
    float* wbuf   = h + TM * HS;                // 2 * KC * WS
    float* bias_s = wbuf + 2 * KC * WS;         // 260
    float* wcol0  = bias_s + 260;               // 256

    int tid = threadIdx.x;
    int tx  = tid & 31;
    int ty  = tid >> 5;
    int s0  = blockIdx.x * TM;

    // load x tile -> h[:, 0:30]
    for (int idx = tid; idx < TM * 30; idx += NTHREADS) {
        int r = idx / 30, k = idx - r * 30;
        h[r * HS + k] = (s0 + r < ns) ? p.x[(size_t)(s0 + r) * 30 + k] : 0.f;
    }
    __syncthreads();

    dense_layer<4, false>(h, wbuf, bias_s, wcol0, p.W[0], p.b[0], 30, 256,
                          tid, tx, ty, out, s0, ns);
#pragma unroll 1
    for (int L = 1; L < 8; ++L)
        dense_layer<4, false>(h, wbuf, bias_s, wcol0, p.W[L], p.b[L], 256, 256,
                              tid, tx, ty, out, s0, ns);
    // layer 8: 256 -> 257. sigma to out, fx into h[:, 0:256]
    dense_layer<4, true>(h, wbuf, bias_s, wcol0, p.W[8], p.b[8], 256, 257,
                         tid, tx, ty, out, s0, ns);

    // append d -> h[:, 256:268]
    for (int idx = tid; idx < TM * 12; idx += NTHREADS) {
        int r = idx / 12, k = idx - r * 12;
        h[r * HS + 256 + k] = (s0 + r < ns) ? p.d[(size_t)(s0 + r) * 12 + k] : 0.f;
    }
    __syncthreads();

    // color layer 0: 268 -> 128
    dense_layer<2, false>(h, wbuf, bias_s, wcol0, p.Wc0, p.bc0, 268, 128,
                          tid, tx, ty, out, s0, ns);

    // color layer 1: 128 -> 3 (tiny; stage Wc1 into smem, direct dot products)
    for (int idx = tid; idx < 128 * 3; idx += NTHREADS) wbuf[idx] = p.Wc1[idx];
    __syncthreads();
    if (tid < TM * 3) {
        int r = tid / 3, cc = tid - r * 3;
        float s = 0.f;
#pragma unroll 4
        for (int k = 0; k < 128; k++) s += h[r * HS + k] * wbuf[k * 3 + cc];
        if (s0 + r < ns)
            out[(size_t)ns + (size_t)(s0 + r) * 3 + cc] = fmaxf(s + p.bc1[cc], 0.f);
    }
}

extern "C" void kernel_launch(void* const* d_in, const int* in_sizes, int n_in,
                              void* d_out, int out_size) {
    Params p;
    p.x = (const float*)d_in[0];
    p.d = (const float*)d_in[1];
    for (int i = 0; i < 9; i++) {
        p.W[i] = (const float*)d_in[2 + 2 * i];
        p.b[i] = (const float*)d_in[3 + 2 * i];
    }
    p.Wc0 = (const float*)d_in[20];
    p.bc0 = (const float*)d_in[21];
    p.Wc1 = (const float*)d_in[22];
    p.bc1 = (const float*)d_in[23];

    int ns = in_sizes[0] / 30;              // 262144
    cudaFuncSetAttribute(nerf_fused_kernel,
                         cudaFuncAttributeMaxDynamicSharedMemorySize, SMEM_BYTES);
    int grid = (ns + TM - 1) / TM;          // 2048
    nerf_fused_kernel<<<grid, NTHREADS, SMEM_BYTES>>>(p, (float*)d_out, ns);
}

// round 3
// speedup vs baseline: 1.0881x; 1.0881x over previous
#include <cuda_runtime.h>
#include <cstdint>

// ---------------------------------------------------------------------------
// NeRF fused MLP, fp32 with packed fma.rn.f32x2 (Blackwell).
// TM=64 samples per CTA, 256 threads, 2 CTAs/SM for latency hiding.
// Activations in SMEM; weights streamed in K=16 chunks, 16B cp.async,
// double-buffered. Template Nw -> cheap index math.
// ---------------------------------------------------------------------------

#define TM        64           // samples per CTA
#define NTHREADS  256          // 8 warps
#define HS        272          // h row stride (floats), fits 268 + pad, even
#define WS        260          // weight chunk col stride (floats), even, %4==0
#define KC        16           // K-chunk depth

#define SMEM_FLOATS (TM*HS + 2*KC*WS + 260 + 256)
#define SMEM_BYTES  (SMEM_FLOATS * 4)

struct Params {
    const float* x;
    const float* d;
    const float* W[9];
    const float* b[9];
    const float* Wc0; const float* bc0;
    const float* Wc1; const float* bc1;
};

// ---- packed fp32x2 helpers -------------------------------------------------
__device__ __forceinline__ unsigned long long splat2(float v) {
    unsigned long long r;
    asm("mov.b64 %0, {%1, %2};" : "=l"(r) : "f"(v), "f"(v));
    return r;
}
__device__ __forceinline__ unsigned long long ffma2(unsigned long long a,
                                                    unsigned long long b,
                                                    unsigned long long c) {
    unsigned long long d;
    asm("fma.rn.f32x2 %0, %1, %2, %3;" : "=l"(d) : "l"(a), "l"(b), "l"(c));
    return d;
}
__device__ __forceinline__ float2 unpack2(unsigned long long v) {
    float2 f;
    asm("mov.b64 {%0, %1}, %2;" : "=f"(f.x), "=f"(f.y) : "l"(v));
    return f;
}

// ---- cp.async helpers ------------------------------------------------------
__device__ __forceinline__ void cp_async16(void* dst, const void* src) {
    unsigned sa = (unsigned)__cvta_generic_to_shared(dst);
    asm volatile("cp.async.cg.shared.global [%0], [%1], 16;" :: "r"(sa), "l"(src));
}
__device__ __forceinline__ void cp_async4(void* dst, const void* src) {
    unsigned sa = (unsigned)__cvta_generic_to_shared(dst);
    asm volatile("cp.async.ca.shared.global [%0], [%1], 4;" :: "r"(sa), "l"(src));
}
__device__ __forceinline__ void cp_commit() { asm volatile("cp.async.commit_group;"); }
__device__ __forceinline__ void cp_wait0()  { asm volatile("cp.async.wait_group 0;"); }
__device__ __forceinline__ void cp_wait1()  { asm volatile("cp.async.wait_group 1;"); }

// Stage one K-chunk of W [kchunk x NW] into smem (col stride WS).
// Non-L8 (NW % 4 == 0): 16-byte copies, compile-time index math.
// L8 (NW=257): scalar path; global col 0 -> wcol0[], cols 1..256 shifted left.
template<int NW, bool L8>
__device__ __forceinline__ void stage_chunk(const float* __restrict__ Wg,
                                            int K, int c,
                                            float* wdst, float* wcol0, int tid) {
    int kbase  = c * KC;
    int kchunk = min(KC, K - kbase);
    if (!L8) {
        constexpr int NW4 = NW / 4;
        int cnt = kchunk * NW4;
        const float4* src = (const float4*)(Wg + (size_t)kbase * NW);
        for (int idx = tid; idx < cnt; idx += NTHREADS) {
            int rr = idx / NW4;             // NW4 is a power of two -> shift
            int cc = idx - rr * NW4;
            cp_async16(&wdst[rr * WS + cc * 4], src + idx);
        }
    } else {
        int cnt = kchunk * NW;
        const float* src = Wg + (size_t)kbase * NW;
        for (int idx = tid; idx < cnt; idx += NTHREADS) {
            int rr = idx / NW;              // constant 257 -> mul-hi sequence
            int cc = idx - rr * NW;
            if (cc == 0) cp_async4(&wcol0[kbase + rr], src + idx);
            else         cp_async4(&wdst[rr * WS + (cc - 1)], src + idx);
        }
    }
}

// One dense layer: h[TM x K] @ W[K x Nw] + b, ReLU, result back into h.
// Thread tile: 8 rows (ty*8..+7) x 2*NP cols (pairs at 2*(tx+32*j)).
// For L8 the main GEMM produces fx (global cols 1..256 -> h cols 0..255) and
// a side pass produces sigma (global col 0) written straight to out[].
template<int NP, int NW, bool L8>
__device__ __forceinline__ void dense_layer(float* h, float* wbuf, float* bias_s,
                                            float* wcol0,
                                            const float* __restrict__ Wg,
                                            const float* __restrict__ bg,
                                            int K,
                                            int tid, int tx, int ty,
                                            float* out, int s0, int ns) {
    const int Ncols = NP * 64;
    for (int j = tid; j < Ncols; j += NTHREADS) bias_s[j] = bg[j + (L8 ? 1 : 0)];

    unsigned long long acc[8][NP];
#pragma unroll
    for (int i = 0; i < 8; i++)
#pragma unroll
        for (int j = 0; j < NP; j++) acc[i][j] = 0ull;

    int nchunks = (K + KC - 1) / KC;
    stage_chunk<NW, L8>(Wg, K, 0, wbuf, wcol0, tid);
    cp_commit();
    int buf = 0;
    for (int c = 0; c < nchunks; c++) {
        if (c + 1 < nchunks) {
            stage_chunk<NW, L8>(Wg, K, c + 1, wbuf + (buf ^ 1) * (KC * WS), wcol0, tid);
            cp_commit();
            cp_wait1();
        } else {
            cp_wait0();
        }
        __syncthreads();   // chunk c visible; buffer buf^1 already restaged above

        int kbase  = c * KC;
        int kchunk = min(KC, K - kbase);        // always even (16/14/12)
        const float* wb = wbuf + buf * (KC * WS);
        for (int kk = 0; kk < kchunk; kk += 2) {
            unsigned long long wv0[NP], wv1[NP];
#pragma unroll
            for (int j = 0; j < NP; j++) {
                int cc = 2 * (tx + 32 * j);
                wv0[j] = *(const unsigned long long*)&wb[kk * WS + cc];
                wv1[j] = *(const unsigned long long*)&wb[(kk + 1) * WS + cc];
            }
#pragma unroll
            for (int i = 0; i < 8; i++) {
                float2 hp = *(const float2*)&h[(ty * 8 + i) * HS + kbase + kk];
                unsigned long long ha = splat2(hp.x);
                unsigned long long hb = splat2(hp.y);
#pragma unroll
                for (int j = 0; j < NP; j++) {
                    acc[i][j] = ffma2(ha, wv0[j], acc[i][j]);
                    acc[i][j] = ffma2(hb, wv1[j], acc[i][j]);
                }
            }
        }
        __syncthreads();   // everyone done reading buffer buf before restage
        buf ^= 1;
    }

    if (L8) {
        // sigma = relu(h . wcol0 + b[0]); h still holds layer-8 input here.
        int r = tid >> 2, q = tid & 3;      // 256 threads -> 64 rows x 4
        float s = 0.f;
#pragma unroll 4
        for (int k = q * 64; k < q * 64 + 64; ++k) s += h[r * HS + k] * wcol0[k];
        s += __shfl_xor_sync(0xffffffffu, s, 1);
        s += __shfl_xor_sync(0xffffffffu, s, 2);
        if (q == 0 && (s0 + r) < ns) out[s0 + r] = fmaxf(s + bg[0], 0.f);
        __syncthreads();   // sigma readers done before h is overwritten with fx
    }

    // writeback relu(acc + bias) into h (aligned float2 stores, conflict-free)
#pragma unroll
    for (int i = 0; i < 8; i++) {
        int r = ty * 8 + i;
#pragma unroll
        for (int j = 0; j < NP; j++) {
            int cc = 2 * (tx + 32 * j);
            float2 a  = unpack2(acc[i][j]);
            float2 b2 = *(const float2*)&bias_s[cc];
            float2 o;
            o.x = fmaxf(a.x + b2.x, 0.f);
            o.y = fmaxf(a.y + b2.y, 0.f);
            *(float2*)&h[r * HS + cc] = o;
        }
    }
    __syncthreads();
}

__global__ void __launch_bounds__(NTHREADS, 2)
nerf_fused_kernel(Params p, float* __restrict__ out, int ns) {
    extern __shared__ float smem[];
    float* h      = smem;                       // TM * HS
    float* wbuf   = h + TM * HS;                // 2 * KC * WS
    float* bias_s = wbuf + 2 * KC * WS;         // 260
    float* wcol0  = bias_s + 260;               // 256

    int tid = threadIdx.x;
    int tx  = tid & 31;
    int ty  = tid >> 5;                         // 0..7 -> 64 rows
    int s0  = blockIdx.x * TM;

    // load x tile -> h[:, 0:30]
    for (int idx = tid; idx < TM * 30; idx += NTHREADS) {
        int r = idx / 30, k = idx - r * 30;
        h[r * HS + k] = (s0 + r < ns) ? p.x[(size_t)(s0 + r) * 30 + k] : 0.f;
    }
    __syncthreads();

    dense_layer<4, 256, false>(h, wbuf, bias_s, wcol0, p.W[0], p.b[0], 30,
                               tid, tx, ty, out, s0, ns);
#pragma unroll 1
    for (int L = 1; L < 8; ++L)
        dense_layer<4, 256, false>(h, wbuf, bias_s, wcol0, p.W[L], p.b[L], 256,
                                   tid, tx, ty, out, s0, ns);
    // layer 8: 256 -> 257. sigma to out, fx into h[:, 0:256]
    dense_layer<4, 257, true>(h, wbuf, bias_s, wcol0, p.W[8], p.b[8], 256,
                              tid, tx, ty, out, s0, ns);

    // append d -> h[:, 256:268]
    for (int idx = tid; idx < TM * 12; idx += NTHREADS) {
        int r = idx / 12, k = idx - r * 12;
        h[r * HS + 256 + k] = (s0 + r < ns) ? p.d[(size_t)(s0 + r) * 12 + k] : 0.f;
    }
    __syncthreads();

    // color layer 0: 268 -> 128
    dense_layer<2, 128, false>(h, wbuf, bias_s, wcol0, p.Wc0, p.bc0, 268,
                               tid, tx, ty, out, s0, ns);

    // color layer 1: 128 -> 3 (tiny; stage Wc1 into smem, direct dot products)
    for (int idx = tid; idx < 128 * 3; idx += NTHREADS) wbuf[idx] = p.Wc1[idx];
    __syncthreads();
    if (tid < TM * 3) {
        int r = tid / 3, cc = tid - r * 3;
        float s = 0.f;
#pragma unroll 4
        for (int k = 0; k < 128; k++) s += h[r * HS + k] * wbuf[k * 3 + cc];
        if (s0 + r < ns)
            out[(size_t)ns + (size_t)(s0 + r) * 3 + cc] = fmaxf(s + p.bc1[cc], 0.f);
    }
}

extern "C" void kernel_launch(void* const* d_in, const int* in_sizes, int n_in,
                              void* d_out, int out_size) {
    Params p;
    p.x = (const float*)d_in[0];
    p.d = (const float*)d_in[1];
    for (int i = 0; i < 9; i++) {
        p.W[i] = (const float*)d_in[2 + 2 * i];
        p.b[i] = (const float*)d_in[3 + 2 * i];
    }
    p.Wc0 = (const float*)d_in[20];
    p.bc0 = (const float*)d_in[21];
    p.Wc1 = (const float*)d_in[22];
    p.bc1 = (const float*)d_in[23];

    int ns = in_sizes[0] / 30;              // 262144
    cudaFuncSetAttribute(nerf_fused_kernel,
                         cudaFuncAttributeMaxDynamicSharedMemorySize, SMEM_BYTES);
    int grid = (ns + TM - 1) / TM;          // 4096
    nerf_fused_kernel<<<grid, NTHREADS, SMEM_BYTES>>>(p, (float*)d_out, ns);
}

// round 4
// speedup vs baseline: 1.0889x; 1.0007x over previous
#include <cuda_runtime.h>
#include <cstdint>

// ---------------------------------------------------------------------------
// NeRF fused MLP, fp32 with packed fma.rn.f32x2 (Blackwell).
// TM=64 samples per CTA, 256 threads, 2 CTAs/SM for latency hiding.
// Activations in SMEM; weights streamed in K=16 chunks, 16B cp.async,
// double-buffered. Template Nw -> cheap index math.
// ---------------------------------------------------------------------------

#define TM        64           // samples per CTA
#define NTHREADS  256          // 8 warps
#define HS        272          // h row stride (floats), fits 268 + pad, even
#define WS        260          // weight chunk col stride (floats), even, %4==0
#define KC        16           // K-chunk depth

#define SMEM_FLOATS (TM*HS + 2*KC*WS + 260 + 256)
#define SMEM_BYTES  (SMEM_FLOATS * 4)

struct Params {
    const float* x;
    const float* d;
    const float* W[9];
    const float* b[9];
    const float* Wc0; const float* bc0;
    const float* Wc1; const float* bc1;
};

// ---- packed fp32x2 helpers -------------------------------------------------
__device__ __forceinline__ unsigned long long splat2(float v) {
    unsigned long long r;
    asm("mov.b64 %0, {%1, %2};" : "=l"(r) : "f"(v), "f"(v));
    return r;
}
__device__ __forceinline__ unsigned long long ffma2(unsigned long long a,
                                                    unsigned long long b,
                                                    unsigned long long c) {
    unsigned long long d;
    asm("fma.rn.f32x2 %0, %1, %2, %3;" : "=l"(d) : "l"(a), "l"(b), "l"(c));
    return d;
}
__device__ __forceinline__ float2 unpack2(unsigned long long v) {
    float2 f;
    asm("mov.b64 {%0, %1}, %2;" : "=f"(f.x), "=f"(f.y) : "l"(v));
    return f;
}

// ---- cp.async helpers ------------------------------------------------------
__device__ __forceinline__ void cp_async16(void* dst, const void* src) {
    unsigned sa = (unsigned)__cvta_generic_to_shared(dst);
    asm volatile("cp.async.cg.shared.global [%0], [%1], 16;" :: "r"(sa), "l"(src));
}
__device__ __forceinline__ void cp_async4(void* dst, const void* src) {
    unsigned sa = (unsigned)__cvta_generic_to_shared(dst);
    asm volatile("cp.async.ca.shared.global [%0], [%1], 4;" :: "r"(sa), "l"(src));
}
__device__ __forceinline__ void cp_commit() { asm volatile("cp.async.commit_group;"); }
__device__ __forceinline__ void cp_wait0()  { asm volatile("cp.async.wait_group 0;"); }
__device__ __forceinline__ void cp_wait1()  { asm volatile("cp.async.wait_group 1;"); }

// Stage one K-chunk of W [kchunk x NW] into smem (col stride WS).
// Non-L8 (NW % 4 == 0): 16-byte copies, compile-time index math.
// L8 (NW=257): scalar path; global col 0 -> wcol0[], cols 1..256 shifted left.
template<int NW, bool L8>
__device__ __forceinline__ void stage_chunk(const float* __restrict__ Wg,
                                            int K, int c,
                                            float* wdst, float* wcol0, int tid) {
    int kbase  = c * KC;
    int kchunk = min(KC, K - kbase);
    if (!L8) {
        constexpr int NW4 = NW / 4;
        int cnt = kchunk * NW4;
        const float4* src = (const float4*)(Wg + (size_t)kbase * NW);
        for (int idx = tid; idx < cnt; idx += NTHREADS) {
            int rr = idx / NW4;             // NW4 is a power of two -> shift
            int cc = idx - rr * NW4;
            cp_async16(&wdst[rr * WS + cc * 4], src + idx);
        }
    } else {
        int cnt = kchunk * NW;
        const float* src = Wg + (size_t)kbase * NW;
        for (int idx = tid; idx < cnt; idx += NTHREADS) {
            int rr = idx / NW;              // constant 257 -> mul-hi sequence
            int cc = idx - rr * NW;
            if (cc == 0) cp_async4(&wcol0[kbase + rr], src + idx);
            else         cp_async4(&wdst[rr * WS + (cc - 1)], src + idx);
        }
    }
}

// One dense layer: h[TM x K] @ W[K x Nw] + b, ReLU, result back into h.
// Thread tile: 8 rows (ty*8..+7) x 2*NP cols (pairs at 2*(tx+32*j)).
// For L8 the main GEMM produces fx (global cols 1..256 -> h cols 0..255) and
// a side pass produces sigma (global col 0) written straight to out[].
template<int NP, int NW, bool L8>
__device__ __forceinline__ void dense_layer(float* h, float* wbuf, float* bias_s,
                                            float* wcol0,
                                            const float* __restrict__ Wg,
                                            const float* __restrict__ bg,
                                            int K,
                                            int tid, int tx, int ty,
                                            float* out, int s0, int ns) {
    const int Ncols = NP * 64;
    for (int j = tid; j < Ncols; j += NTHREADS) bias_s[j] = bg[j + (L8 ? 1 : 0)];

    unsigned long long acc[8][NP];
#pragma unroll
    for (int i = 0; i < 8; i++)
#pragma unroll
        for (int j = 0; j < NP; j++) acc[i][j] = 0ull;

    int nchunks = (K + KC - 1) / KC;
    stage_chunk<NW, L8>(Wg, K, 0, wbuf, wcol0, tid);
    cp_commit();
    int buf = 0;
    for (int c = 0; c < nchunks; c++) {
        if (c + 1 < nchunks) {
            stage_chunk<NW, L8>(Wg, K, c + 1, wbuf + (buf ^ 1) * (KC * WS), wcol0, tid);
            cp_commit();
            cp_wait1();
        } else {
            cp_wait0();
        }
        __syncthreads();   // chunk c visible; buffer buf^1 already restaged above

        int kbase  = c * KC;
        int kchunk = min(KC, K - kbase);        // always even (16/14/12)
        const float* wb = wbuf + buf * (KC * WS);
        for (int kk = 0; kk < kchunk; kk += 2) {
            unsigned long long wv0[NP], wv1[NP];
#pragma unroll
            for (int j = 0; j < NP; j++) {
                int cc = 2 * (tx + 32 * j);
                wv0[j] = *(const unsigned long long*)&wb[kk * WS + cc];
                wv1[j] = *(const unsigned long long*)&wb[(kk + 1) * WS + cc];
            }
#pragma unroll
            for (int i = 0; i < 8; i++) {
                float2 hp = *(const float2*)&h[(ty * 8 + i) * HS + kbase + kk];
                unsigned long long ha = splat2(hp.x);
                unsigned long long hb = splat2(hp.y);
#pragma unroll
                for (int j = 0; j < NP; j++) {
                    acc[i][j] = ffma2(ha, wv0[j], acc[i][j]);
                    acc[i][j] = ffma2(hb, wv1[j], acc[i][j]);
                }
            }
        }
        __syncthreads();   // everyone done reading buffer buf before restage
        buf ^= 1;
    }

    if (L8) {
        // sigma = relu(h . wcol0 + b[0]); h still holds layer-8 input here.
        int r = tid >> 2, q = tid & 3;      // 256 threads -> 64 rows x 4
        float s = 0.f;
#pragma unroll 4
        for (int k = q * 64; k < q * 64 + 64; ++k) s += h[r * HS + k] * wcol0[k];
        s += __shfl_xor_sync(0xffffffffu, s, 1);
        s += __shfl_xor_sync(0xffffffffu, s, 2);
        if (q == 0 && (s0 + r) < ns) out[s0 + r] = fmaxf(s + bg[0], 0.f);
        __syncthreads();   // sigma readers done before h is overwritten with fx
    }

    // writeback relu(acc + bias) into h (aligned float2 stores, conflict-free)
#pragma unroll
    for (int i = 0; i < 8; i++) {
        int r = ty * 8 + i;
#pragma unroll
        for (int j = 0; j < NP; j++) {
            int cc = 2 * (tx + 32 * j);
            float2 a  = unpack2(acc[i][j]);
            float2 b2 = *(const float2*)&bias_s[cc];
            float2 o;
            o.x = fmaxf(a.x + b2.x, 0.f);
            o.y = fmaxf(a.y + b2.y, 0.f);
            *(float2*)&h[r * HS + cc] = o;
        }
    }
    __syncthreads();
}

__global__ void __launch_bounds__(NTHREADS, 2)
nerf_fused_kernel(Params p, float* __restrict__ out, int ns) {
    extern __shared__ float smem[];
    float* h      = smem;                       // TM * HS
    float* wbuf   = h + TM * HS;                // 2 * KC * WS
    float* bias_s = wbuf + 2 * KC * WS;         // 260
    float* wcol0  = bias_s + 260;               // 256

    int tid = threadIdx.x;
    int tx  = tid & 31;
    int ty  = tid >> 5;                         // 0..7 -> 64 rows
    int s0  = blockIdx.x * TM;

    // load x tile -> h[:, 0:30]
    for (int idx = tid; idx < TM * 30; idx += NTHREADS) {
        int r = idx / 30, k = idx - r * 30;
        h[r * HS + k] = (s0 + r < ns) ? p.x[(size_t)(s0 + r) * 30 + k] : 0.f;
    }
    __syncthreads();

    dense_layer<4, 256, false>(h, wbuf, bias_s, wcol0, p.W[0], p.b[0], 30,
                               tid, tx, ty, out, s0, ns);
#pragma unroll 1
    for (int L = 1; L < 8; ++L)
        dense_layer<4, 256, false>(h, wbuf, bias_s, wcol0, p.W[L], p.b[L], 256,
                                   tid, tx, ty, out, s0, ns);
    // layer 8: 256 -> 257. sigma to out, fx into h[:, 0:256]
    dense_layer<4, 257, true>(h, wbuf, bias_s, wcol0, p.W[8], p.b[8], 256,
                              tid, tx, ty, out, s0, ns);

    // append d -> h[:, 256:268]
    for (int idx = tid; idx < TM * 12; idx += NTHREADS) {
        int r = idx / 12, k = idx - r * 12;
        h[r * HS + 256 + k] = (s0 + r < ns) ? p.d[(size_t)(s0 + r) * 12 + k] : 0.f;
    }
    __syncthreads();

    // color layer 0: 268 -> 128
    dense_layer<2, 128, false>(h, wbuf, bias_s, wcol0, p.Wc0, p.bc0, 268,
                               tid, tx, ty, out, s0, ns);

    // color layer 1: 128 -> 3 (tiny; stage Wc1 into smem, direct dot products)
    for (int idx = tid; idx < 128 * 3; idx += NTHREADS) wbuf[idx] = p.Wc1[idx];
    __syncthreads();
    if (tid < TM * 3) {
        int r = tid / 3, cc = tid - r * 3;
        float s = 0.f;
#pragma unroll 4
        for (int k = 0; k < 128; k++) s += h[r * HS + k] * wbuf[k * 3 + cc];
        if (s0 + r < ns)
            out[(size_t)ns + (size_t)(s0 + r) * 3 + cc] = fmaxf(s + p.bc1[cc], 0.f);
    }
}

extern "C" void kernel_launch(void* const* d_in, const int* in_sizes, int n_in,
                              void* d_out, int out_size) {
    Params p;
    p.x = (const float*)d_in[0];
    p.d = (const float*)d_in[1];
    for (int i = 0; i < 9; i++) {
        p.W[i] = (const float*)d_in[2 + 2 * i];
        p.b[i] = (const float*)d_in[3 + 2 * i];
    }
    p.Wc0 = (const float*)d_in[20];
    p.bc0 = (const float*)d_in[21];
    p.Wc1 = (const float*)d_in[22];
    p.bc1 = (const float*)d_in[23];

    int ns = in_sizes[0] / 30;              // 262144
    cudaFuncSetAttribute(nerf_fused_kernel,
                         cudaFuncAttributeMaxDynamicSharedMemorySize, SMEM_BYTES);
    int grid = (ns + TM - 1) / TM;          // 4096
    nerf_fused_kernel<<<grid, NTHREADS, SMEM_BYTES>>>(p, (float*)d_out, ns);
}

// round 6
// speedup vs baseline: 1.6626x; 1.5269x over previous
#include <cuda_runtime.h>
#include <cuda_fp16.h>
#include <cstdint>

// ---------------------------------------------------------------------------
// NeRF fused MLP via mma.sync m16n8k16 (f16 in, fp32 acc), hi/lo split:
// D = Ahi*Bhi + Alo*Bhi + Ahi*Blo. 128 samples/CTA, 512 threads (16 warps,
// 4x4 warp tile: each warp 32 rows x 64 cols). Activations hi/lo in SMEM.
// ---------------------------------------------------------------------------

#define NT 512

// A: [128][280] halves, row stride 560 B (bank-shift 12 -> conflict-free)
#define SA_B   560
#define A_HI   0
#define A_LO   71680
// W chunk: [256 n][72 k] halves, row stride 144 B (bank-shift 4)
#define SW_B   144
#define W_HI   143360
#define W_LO   180224
#define BIAS   217088
#define WCOL0  218112
#define WC1O   219136
// hc f32 [128][132] overlaid on W region (dead during head)
#define HCOFF  143360
#define SHC_B  528
#define SMEM_SZ 220672

struct Params {
    const float* x; const float* d;
    const float* W[9]; const float* b[9];
    const float* Wc0; const float* bc0;
    const float* Wc1; const float* bc1;
};

__device__ __forceinline__ void mma16816(float c[4], uint32_t a0, uint32_t a1,
                                         uint32_t a2, uint32_t a3,
                                         uint32_t b0, uint32_t b1) {
    asm("mma.sync.aligned.m16n8k16.row.col.f32.f16.f16.f32 "
        "{%0,%1,%2,%3}, {%4,%5,%6,%7}, {%8,%9}, {%0,%1,%2,%3};"
        : "+f"(c[0]), "+f"(c[1]), "+f"(c[2]), "+f"(c[3])
        : "r"(a0), "r"(a1), "r"(a2), "r"(a3), "r"(b0), "r"(b1));
}
__device__ __forceinline__ uint32_t pack2(__half a, __half b) {
    return (uint32_t)__half_as_ushort(a) | ((uint32_t)__half_as_ushort(b) << 16);
}
__device__ __forceinline__ void hsplit(float v, __half& h, __half& l) {
    h = __float2half_rn(v);
    l = __float2half_rn(v - __half2float(h));
}
__device__ __forceinline__ uint32_t packsplit(float v0, float v1, uint32_t& lo) {
    __half h0, l0, h1, l1;
    hsplit(v0, h0, l0); hsplit(v1, h1, l1);
    lo = pack2(l0, l1);
    return pack2(h0, h1);
}

// ---- W staging: one 64-K chunk, global [k][ldw] -> smem [n][k] hi/lo -------
template<int NW>
__device__ __forceinline__ void stage_W(char* g, const float* __restrict__ Wg,
                                        int ldw, int shift, int Klayer,
                                        int kbase, int t) {
    const int total = NW * 32;                 // (n, k-pair) units
#pragma unroll 1
    for (int idx = t; idx < total; idx += NT) {
        int n  = idx & (NW - 1);
        int kp = idx / NW;
        int k  = kp * 2;
        int gk = kbase + k;
        float v0 = (gk     < Klayer) ? __ldg(&Wg[(size_t)gk * ldw + n + shift])       : 0.f;
        float v1 = (gk + 1 < Klayer) ? __ldg(&Wg[(size_t)(gk + 1) * ldw + n + shift]) : 0.f;
        uint32_t lo, hi = packsplit(v0, v1, lo);
        *(uint32_t*)(g + W_HI + n * SW_B + k * 2) = hi;
        *(uint32_t*)(g + W_LO + n * SW_B + k * 2) = lo;
    }
}

// ---- GEMM: acc += (A[128 x K]) @ (W[K x NW]); per-warp 32 x (NTILES*8) -----
template<int NTILES>
__device__ __forceinline__ void gemm_layer(char* g, const float* __restrict__ Wg,
                                           int ldw, int shift, int K, int Klayer,
                                           int t, int lane, int wm, int wn,
                                           float acc[][4]) {
#pragma unroll
    for (int i = 0; i < 2 * NTILES; i++)
#pragma unroll
        for (int j = 0; j < 4; j++) acc[i][j] = 0.f;

    const int g8 = lane >> 2, tig = lane & 3;
    const int nch = (K + 63) >> 6;
#pragma unroll 1
    for (int c = 0; c < nch; c++) {
        __syncthreads();                       // prior chunk mma reads done
        stage_W<NTILES * 32>(g, Wg, ldw, shift, Klayer, c * 64, t);
        __syncthreads();
        int ksteps = min(4, (K - c * 64 + 15) >> 4);
#pragma unroll 1
        for (int ks = 0; ks < ksteps; ks++) {
            int kg = c * 64 + ks * 16;         // A global k
            int kl = ks * 16;                  // W local k
            uint32_t ah[2][4], al[2][4];
#pragma unroll
            for (int mt = 0; mt < 2; mt++) {
                int r0 = wm * 32 + mt * 16 + g8;
                const char* ba = g + r0 * SA_B + (kg + tig * 2) * 2;
                ah[mt][0] = *(const uint32_t*)(ba + A_HI);
                ah[mt][1] = *(const uint32_t*)(ba + A_HI + 8 * SA_B);
                ah[mt][2] = *(const uint32_t*)(ba + A_HI + 16);
                ah[mt][3] = *(const uint32_t*)(ba + A_HI + 8 * SA_B + 16);
                al[mt][0] = *(const uint32_t*)(ba + A_LO);
                al[mt][1] = *(const uint32_t*)(ba + A_LO + 8 * SA_B);
                al[mt][2] = *(const uint32_t*)(ba + A_LO + 16);
                al[mt][3] = *(const uint32_t*)(ba + A_LO + 8 * SA_B + 16);
            }
#pragma unroll
            for (int nt = 0; nt < NTILES; nt++) {
                int n0 = wn * (NTILES * 8) + nt * 8 + g8;
                const char* bw = g + n0 * SW_B + (kl + tig * 2) * 2;
                uint32_t bh0 = *(const uint32_t*)(bw + W_HI);
                uint32_t bh1 = *(const uint32_t*)(bw + W_HI + 16);
                uint32_t bl0 = *(const uint32_t*)(bw + W_LO);
                uint32_t bl1 = *(const uint32_t*)(bw + W_LO + 16);
#pragma unroll
                for (int mt = 0; mt < 2; mt++) {
                    mma16816(acc[mt * NTILES + nt], ah[mt][0], ah[mt][1], ah[mt][2], ah[mt][3], bh0, bh1);
                    mma16816(acc[mt * NTILES + nt], al[mt][0], al[mt][1], al[mt][2], al[mt][3], bh0, bh1);
                    mma16816(acc[mt * NTILES + nt], ah[mt][0], ah[mt][1], ah[mt][2], ah[mt][3], bl0, bl1);
                }
            }
        }
    }
    __syncthreads();                           // all mma A-reads done
}

// ---- epilogue: bias + ReLU, hi/lo split back into A ------------------------
template<int NTILES>
__device__ __forceinline__ void epilogue_A(char* g, int lane, int wm, int wn,
                                           float acc[][4]) {
    const int g8 = lane >> 2, tig = lane & 3;
    const float* bias = (const float*)(g + BIAS);
#pragma unroll
    for (int mt = 0; mt < 2; mt++) {
#pragma unroll
        for (int nt = 0; nt < NTILES; nt++) {
            int r1 = wm * 32 + mt * 16 + g8, r2 = r1 + 8;
            int cb = wn * (NTILES * 8) + nt * 8 + tig * 2;
            float* a = acc[mt * NTILES + nt];
            float b0 = bias[cb], b1 = bias[cb + 1];
            uint32_t lo, hi;
            hi = packsplit(fmaxf(a[0] + b0, 0.f), fmaxf(a[1] + b1, 0.f), lo);
            *(uint32_t*)(g + A_HI + r1 * SA_B + cb * 2) = hi;
            *(uint32_t*)(g + A_LO + r1 * SA_B + cb * 2) = lo;
            hi = packsplit(fmaxf(a[2] + b0, 0.f), fmaxf(a[3] + b1, 0.f), lo);
            *(uint32_t*)(g + A_HI + r2 * SA_B + cb * 2) = hi;
            *(uint32_t*)(g + A_LO + r2 * SA_B + cb * 2) = lo;
        }
    }
    __syncthreads();
}

// color epilogue: bias + ReLU -> hc f32 (overlaid on W region)
__device__ __forceinline__ void epilogue_HC(char* g, int lane, int wm, int wn,
                                            float acc[][4]) {
    const int g8 = lane >> 2, tig = lane & 3;
    const float* bias = (const float*)(g + BIAS);
#pragma unroll
    for (int mt = 0; mt < 2; mt++) {
#pragma unroll
        for (int nt = 0; nt < 4; nt++) {
            int r1 = wm * 32 + mt * 16 + g8, r2 = r1 + 8;
            int cb = wn * 32 + nt * 8 + tig * 2;
            float* a = acc[mt * 4 + nt];
            float b0 = bias[cb], b1 = bias[cb + 1];
            float2 v1 = make_float2(fmaxf(a[0] + b0, 0.f), fmaxf(a[1] + b1, 0.f));
            float2 v2 = make_float2(fmaxf(a[2] + b0, 0.f), fmaxf(a[3] + b1, 0.f));
            *(float2*)(g + HCOFF + r1 * SHC_B + cb * 4) = v1;
            *(float2*)(g + HCOFF + r2 * SHC_B + cb * 4) = v2;
        }
    }
    __syncthreads();
}

// ---- kernel ----------------------------------------------------------------
__global__ void __launch_bounds__(NT, 1)
nerf_hmma_kernel(Params p, float* __restrict__ out, int ns) {
    extern __shared__ char g[];
    int t = threadIdx.x, lane = t & 31, w = t >> 5;
    int wm = w & 3, wn = w >> 2;
    int s0 = blockIdx.x * 128;
    float acc[16][4];

    // stage x -> A cols 0..31 (k>=30 zero)
    {
        int r = t >> 2, q = t & 3;             // 4 threads/row, 8 k each
        const float* xr = p.x + (size_t)(s0 + r) * 30;
#pragma unroll
        for (int pr = 0; pr < 4; pr++) {
            int k = q * 8 + pr * 2;
            float v0 = (k     < 30) ? xr[k]     : 0.f;
            float v1 = (k + 1 < 30) ? xr[k + 1] : 0.f;
            uint32_t lo, hi = packsplit(v0, v1, lo);
            *(uint32_t*)(g + A_HI + r * SA_B + k * 2) = hi;
            *(uint32_t*)(g + A_LO + r * SA_B + k * 2) = lo;
        }
    }
    if (t < 256) ((float*)(g + BIAS))[t] = __ldg(&p.b[0][t]);

    // layer 0: 30 -> 256  (K padded to 32)
    gemm_layer<8>(g, p.W[0], 256, 0, 32, 30, t, lane, wm, wn, acc);
    epilogue_A<8>(g, lane, wm, wn, acc);

    // layers 1..7: 256 -> 256
#pragma unroll 1
    for (int L = 1; L <= 7; L++) {
        if (t < 256) ((float*)(g + BIAS))[t] = __ldg(&p.b[L][t]);
        gemm_layer<8>(g, p.W[L], 256, 0, 256, 256, t, lane, wm, wn, acc);
        epilogue_A<8>(g, lane, wm, wn, acc);
    }

    // layer 8: 256 -> 257 (GEMM cols 1..256; col 0 = sigma scalar path)
    if (t < 256) {
        ((float*)(g + BIAS))[t]  = __ldg(&p.b[8][t + 1]);
        ((float*)(g + WCOL0))[t] = __ldg(&p.W[8][(size_t)t * 257]);
    }
    gemm_layer<8>(g, p.W[8], 257, 1, 256, 256, t, lane, wm, wn, acc);
    {   // sigma from A (layer-8 input, hi+lo) before epilogue overwrites A
        int r = t >> 2, q = t & 3;
        const float* wc = (const float*)(g + WCOL0);
        float s = 0.f;
#pragma unroll 4
        for (int k = q * 64; k < q * 64 + 64; k++) {
            float hv = __half2float(*(const __half*)(g + A_HI + r * SA_B + k * 2))
                     + __half2float(*(const __half*)(g + A_LO + r * SA_B + k * 2));
            s += hv * wc[k];
        }
        s += __shfl_xor_sync(0xffffffffu, s, 1);
        s += __shfl_xor_sync(0xffffffffu, s, 2);
        if (!q && (s0 + r) < ns) out[s0 + r] = fmaxf(s + __ldg(&p.b[8][0]), 0.f);
        __syncthreads();
    }
    epilogue_A<8>(g, lane, wm, wn, acc);       // fx -> A cols 0..255

    // stage d -> A cols 256..267, zero 268..271
    {
        int r = t >> 2, q = t & 3;             // 4 k each -> covers 256..271
        const float* dr = p.d + (size_t)(s0 + r) * 12;
#pragma unroll
        for (int pr = 0; pr < 2; pr++) {
            int kg = 256 + q * 4 + pr * 2;
            float v0 = (kg     < 268) ? dr[kg - 256]     : 0.f;
            float v1 = (kg + 1 < 268) ? dr[kg + 1 - 256] : 0.f;
            uint32_t lo, hi = packsplit(v0, v1, lo);
            *(uint32_t*)(g + A_HI + r * SA_B + kg * 2) = hi;
            *(uint32_t*)(g + A_LO + r * SA_B + kg * 2) = lo;
        }
    }
    if (t < 128) ((float*)(g + BIAS))[t] = __ldg(&p.bc0[t]);
    if (t < 384) ((float*)(g + WC1O))[t] = __ldg(&p.Wc1[t]);

    // color layer 0: 268 -> 128 (K padded to 272)
    gemm_layer<4>(g, p.Wc0, 128, 0, 272, 268, t, lane, wm, wn, acc);
    epilogue_HC(g, lane, wm, wn, acc);

    // head: c = relu(hc @ Wc1 + bc1)
    if (t < 384) {
        int r = t / 3, j = t - r * 3;
        const float* hc  = (const float*)(g + HCOFF + r * SHC_B);
        const float* wc1 = (const float*)(g + WC1O);
        float s = 0.f;
#pragma unroll 4
        for (int k = 0; k < 128; k++) s += hc[k] * wc1[k * 3 + j];
        if ((s0 + r) < ns)
            out[(size_t)ns + (size_t)(s0 + r) * 3 + j] = fmaxf(s + __ldg(&p.bc1[j]), 0.f);
    }
}

extern "C" void kernel_launch(void* const* d_in, const int* in_sizes, int n_in,
                              void* d_out, int out_size) {
    Params p;
    p.x = (const float*)d_in[0];
    p.d = (const float*)d_in[1];
    for (int i = 0; i < 9; i++) {
        p.W[i] = (const float*)d_in[2 + 2 * i];
        p.b[i] = (const float*)d_in[3 + 2 * i];
    }
    p.Wc0 = (const float*)d_in[20];
    p.bc0 = (const float*)d_in[21];
    p.Wc1 = (const float*)d_in[22];
    p.bc1 = (const float*)d_in[23];

    int ns = in_sizes[0] / 30;   // 262144
    cudaFuncSetAttribute(nerf_hmma_kernel,
                         cudaFuncAttributeMaxDynamicSharedMemorySize, SMEM_SZ);
    int grid = (ns + 127) / 128; // 2048
    nerf_hmma_kernel<<<grid, NT, SMEM_SZ>>>(p, (float*)d_out, ns);
}

// round 7
// speedup vs baseline: 2.3620x; 1.4207x over previous
#include <cuda_runtime.h>
#include <cuda_fp16.h>
#include <cstdint>

// ---------------------------------------------------------------------------
// NeRF fused MLP via mma.sync m16n8k16 (f16 in, fp32 acc), hi/lo split:
// D = Ahi*Bhi + Alo*Bhi + Ahi*Blo.  128 samples/CTA, 512 threads, 4x4 warps.
// Weights pre-converted ONCE (prologue kernel) into __device__ hi/lo blobs in
// per-chunk [n][k] order; main kernel streams them with double-buffered
// 16B cp.async fully overlapped with MMA.
// ---------------------------------------------------------------------------

#define NT 512

// A: [128][280] halves, row stride 560 B (bank shift 12 -> conflict-free)
#define SA_B   560
#define A_HI   0
#define A_LO   71680
// W double buffer: per buffer {hi,lo}, each 256 n-rows x 80 B (64 data+16 pad)
#define W_BASE 143360
#define W_BUFB 40960            // byte stride between buffer 0 and 1
#define W_LOD  20480            // lo plane offset within a buffer
#define BIAS   225280
#define WCOL0  226304
#define WC1O   227328
#define SMEM_SZ 228864
// hc f32 [128][132] overlaid on W region (dead during head)
#define HCOFF  143360
#define SHC_B  528

// weight blob layout (halves, per plane):
//  L0   @ 0      : 256n x 32k (k>=30 zero)                 = 8192
//  L1-7 @ 8192+(L-1)*65536 : 8 chunks x (256n x 32k)       = 65536 each
//  L8   @ 466944 : cols 1..256 shifted                     = 65536
//  Wc0  @ 532480 : 8 chunks x (128n x 32k) + 1 x (128n x 16k), k>=268 zero
#define BLOB_N 567296
__device__ __half g_whi[BLOB_N];
__device__ __half g_wlo[BLOB_N];

struct Params {
    const float* x; const float* d;
    const float* W[9]; const float* b[9];
    const float* Wc0; const float* bc0;
    const float* Wc1; const float* bc1;
};

__device__ __forceinline__ void mma16816(float c[4], uint32_t a0, uint32_t a1,
                                         uint32_t a2, uint32_t a3,
                                         uint32_t b0, uint32_t b1) {
    asm("mma.sync.aligned.m16n8k16.row.col.f32.f16.f16.f32 "
        "{%0,%1,%2,%3}, {%4,%5,%6,%7}, {%8,%9}, {%0,%1,%2,%3};"
        : "+f"(c[0]), "+f"(c[1]), "+f"(c[2]), "+f"(c[3])
        : "r"(a0), "r"(a1), "r"(a2), "r"(a3), "r"(b0), "r"(b1));
}
__device__ __forceinline__ uint32_t pack2(__half a, __half b) {
    return (uint32_t)__half_as_ushort(a) | ((uint32_t)__half_as_ushort(b) << 16);
}
__device__ __forceinline__ void hsplit(float v, __half& h, __half& l) {
    h = __float2half_rn(v);
    l = __float2half_rn(v - __half2float(h));
}
__device__ __forceinline__ uint32_t packsplit(float v0, float v1, uint32_t& lo) {
    __half h0, l0, h1, l1;
    hsplit(v0, h0, l0); hsplit(v1, h1, l1);
    lo = pack2(l0, l1);
    return pack2(h0, h1);
}
#define CP_COMMIT() asm volatile("cp.async.commit_group;")
#define CP_WAIT(n)  asm volatile("cp.async.wait_group %0;" :: "n"(n))

// ---- prologue: convert all weights f32 -> hi/lo f16 blobs ------------------
__global__ void convert_weights(Params p) {
    int idx = blockIdx.x * blockDim.x + threadIdx.x;
    if (idx >= BLOB_N) return;
    float v;
    if (idx < 8192) {                       // L0
        int n = idx >> 5, kk = idx & 31;
        v = (kk < 30) ? __ldg(&p.W[0][kk * 256 + n]) : 0.f;
    } else if (idx < 532480) {              // L1..L8
        int i = idx - 8192;
        int L = 1 + i / 65536;
        int r = i & 65535;
        int gk = (r >> 13) * 32 + (r & 31);
        int n  = (r >> 5) & 255;
        v = (L <= 7) ? __ldg(&p.W[L][(size_t)gk * 256 + n])
                     : __ldg(&p.W[8][(size_t)gk * 257 + n + 1]);
    } else {                                // Wc0
        int i = idx - 532480;
        if (i < 32768) {
            int gk = (i >> 12) * 32 + (i & 31);
            int n  = (i >> 5) & 127;
            v = __ldg(&p.Wc0[(size_t)gk * 128 + n]);
        } else {
            int j = i - 32768;
            int n = j >> 4, gk = 256 + (j & 15);
            v = (gk < 268) ? __ldg(&p.Wc0[(size_t)gk * 128 + n]) : 0.f;
        }
    }
    __half h, l; hsplit(v, h, l);
    g_whi[idx] = h; g_wlo[idx] = l;
}

// ---- stage one chunk: blob -> smem W buffer (16B cp.async) -----------------
__device__ __forceinline__ void stage_chunk(uint32_t dstb, const __half* hs,
                                            const __half* ls, int NW, int kw,
                                            int t) {
    int cpr = kw >> 3;                       // 16B copies per row: 4 or 2
    int sh  = (kw == 32) ? 2 : 1;
    int total = NW * cpr;
#pragma unroll 1
    for (int idx = t; idx < 2 * total; idx += NT) {
        int pl = (idx >= total) ? 1 : 0;
        int i  = idx - pl * total;
        int n  = i >> sh, j = i & (cpr - 1);
        const __half* s = (pl ? ls : hs) + n * kw + j * 8;
        uint32_t dd = dstb + pl * W_LOD + n * 80 + j * 16;
        asm volatile("cp.async.cg.shared.global [%0], [%1], 16;"
                     :: "r"(dd), "l"(s));
    }
}

// ---- GEMM: acc = A[128 x K] @ W[K x NW], double-buffered W pipeline --------
template<int NTILES>
__device__ __forceinline__ void gemm_layer(char* g, uint32_t sb, int base,
                                           int K, int t, int lane, int wm,
                                           int wn, float acc[][4]) {
    constexpr int NW = NTILES * 32;
#pragma unroll
    for (int i = 0; i < 2 * NTILES; i++)
#pragma unroll
        for (int j = 0; j < 4; j++) acc[i][j] = 0.f;

    const int g8 = lane >> 2, tig = lane & 3;
    const int nch = (K + 31) >> 5;

    stage_chunk(sb + W_BASE, g_whi + base, g_wlo + base, NW, min(32, K), t);
    CP_COMMIT();
#pragma unroll 1
    for (int c = 0; c < nch; c++) {
        if (c + 1 < nch) {
            int kw2 = min(32, K - (c + 1) * 32);
            int off = base + NW * 32 * (c + 1);
            stage_chunk(sb + W_BASE + ((c + 1) & 1) * W_BUFB,
                        g_whi + off, g_wlo + off, NW, kw2, t);
            CP_COMMIT();
            CP_WAIT(1);
        } else {
            CP_WAIT(0);
        }
        __syncthreads();

        const char* wh = g + W_BASE + (c & 1) * W_BUFB;
        int ksteps = min(32, K - c * 32) >> 4;
#pragma unroll 1
        for (int ks = 0; ks < ksteps; ks++) {
            int kg = c * 32 + ks * 16;
            int kl = ks * 16;
            uint32_t ah[2][4], al[2][4];
#pragma unroll
            for (int mt = 0; mt < 2; mt++) {
                int r0 = wm * 32 + mt * 16 + g8;
                const char* ba = g + r0 * SA_B + (kg + tig * 2) * 2;
                ah[mt][0] = *(const uint32_t*)(ba + A_HI);
                ah[mt][1] = *(const uint32_t*)(ba + A_HI + 8 * SA_B);
                ah[mt][2] = *(const uint32_t*)(ba + A_HI + 16);
                ah[mt][3] = *(const uint32_t*)(ba + A_HI + 8 * SA_B + 16);
                al[mt][0] = *(const uint32_t*)(ba + A_LO);
                al[mt][1] = *(const uint32_t*)(ba + A_LO + 8 * SA_B);
                al[mt][2] = *(const uint32_t*)(ba + A_LO + 16);
                al[mt][3] = *(const uint32_t*)(ba + A_LO + 8 * SA_B + 16);
            }
#pragma unroll
            for (int nt = 0; nt < NTILES; nt++) {
                int n0 = wn * (NTILES * 8) + nt * 8 + g8;
                const char* bw = wh + n0 * 80 + (kl + tig * 2) * 2;
                uint32_t bh0 = *(const uint32_t*)(bw);
                uint32_t bh1 = *(const uint32_t*)(bw + 16);
                uint32_t bl0 = *(const uint32_t*)(bw + W_LOD);
                uint32_t bl1 = *(const uint32_t*)(bw + W_LOD + 16);
#pragma unroll
                for (int mt = 0; mt < 2; mt++) {
                    mma16816(acc[mt * NTILES + nt], ah[mt][0], ah[mt][1], ah[mt][2], ah[mt][3], bh0, bh1);
                    mma16816(acc[mt * NTILES + nt], al[mt][0], al[mt][1], al[mt][2], al[mt][3], bh0, bh1);
                    mma16816(acc[mt * NTILES + nt], ah[mt][0], ah[mt][1], ah[mt][2], ah[mt][3], bl0, bl1);
                }
            }
        }
        __syncthreads();   // mma reads of this buffer done before restage
    }
}

// ---- epilogue: bias + ReLU, hi/lo split back into A ------------------------
template<int NTILES>
__device__ __forceinline__ void epilogue_A(char* g, int lane, int wm, int wn,
                                           float acc[][4]) {
    const int g8 = lane >> 2, tig = lane & 3;
    const float* bias = (const float*)(g + BIAS);
#pragma unroll
    for (int mt = 0; mt < 2; mt++) {
#pragma unroll
        for (int nt = 0; nt < NTILES; nt++) {
            int r1 = wm * 32 + mt * 16 + g8, r2 = r1 + 8;
            int cb = wn * (NTILES * 8) + nt * 8 + tig * 2;
            float* a = acc[mt * NTILES + nt];
            float b0 = bias[cb], b1 = bias[cb + 1];
            uint32_t lo, hi;
            hi = packsplit(fmaxf(a[0] + b0, 0.f), fmaxf(a[1] + b1, 0.f), lo);
            *(uint32_t*)(g + A_HI + r1 * SA_B + cb * 2) = hi;
            *(uint32_t*)(g + A_LO + r1 * SA_B + cb * 2) = lo;
            hi = packsplit(fmaxf(a[2] + b0, 0.f), fmaxf(a[3] + b1, 0.f), lo);
            *(uint32_t*)(g + A_HI + r2 * SA_B + cb * 2) = hi;
            *(uint32_t*)(g + A_LO + r2 * SA_B + cb * 2) = lo;
        }
    }
    __syncthreads();
}

// color epilogue: bias + ReLU -> hc f32 (overlaid on W region)
__device__ __forceinline__ void epilogue_HC(char* g, int lane, int wm, int wn,
                                            float acc[][4]) {
    const int g8 = lane >> 2, tig = lane & 3;
    const float* bias = (const float*)(g + BIAS);
#pragma unroll
    for (int mt = 0; mt < 2; mt++) {
#pragma unroll
        for (int nt = 0; nt < 4; nt++) {
            int r1 = wm * 32 + mt * 16 + g8, r2 = r1 + 8;
            int cb = wn * 32 + nt * 8 + tig * 2;
            float* a = acc[mt * 4 + nt];
            float b0 = bias[cb], b1 = bias[cb + 1];
            float2 v1 = make_float2(fmaxf(a[0] + b0, 0.f), fmaxf(a[1] + b1, 0.f));
            float2 v2 = make_float2(fmaxf(a[2] + b0, 0.f), fmaxf(a[3] + b1, 0.f));
            *(float2*)(g + HCOFF + r1 * SHC_B + cb * 4) = v1;
            *(float2*)(g + HCOFF + r2 * SHC_B + cb * 4) = v2;
        }
    }
    __syncthreads();
}

// ---- main kernel -----------------------------------------------------------
__global__ void __launch_bounds__(NT, 1)
nerf_hmma_kernel(Params p, float* __restrict__ out, int ns) {
    extern __shared__ char g[];
    uint32_t sb = (uint32_t)__cvta_generic_to_shared(g);
    int t = threadIdx.x, lane = t & 31, w = t >> 5;
    int wm = w & 3, wn = w >> 2;
    int s0 = blockIdx.x * 128;
    float acc[16][4];

    // stage x -> A cols 0..31 (k>=30 zero)
    {
        int r = t >> 2, q = t & 3;
        const float* xr = p.x + (size_t)(s0 + r) * 30;
#pragma unroll
        for (int pr = 0; pr < 4; pr++) {
            int k = q * 8 + pr * 2;
            float v0 = (k     < 30) ? xr[k]     : 0.f;
            float v1 = (k + 1 < 30) ? xr[k + 1] : 0.f;
            uint32_t lo, hi = packsplit(v0, v1, lo);
            *(uint32_t*)(g + A_HI + r * SA_B + k * 2) = hi;
            *(uint32_t*)(g + A_LO + r * SA_B + k * 2) = lo;
        }
    }
    if (t < 256) ((float*)(g + BIAS))[t] = __ldg(&p.b[0][t]);
    __syncthreads();

    // layer 0: 30 -> 256
    gemm_layer<8>(g, sb, 0, 32, t, lane, wm, wn, acc);
    epilogue_A<8>(g, lane, wm, wn, acc);

    // layers 1..7: 256 -> 256
#pragma unroll 1
    for (int L = 1; L <= 7; L++) {
        if (t < 256) ((float*)(g + BIAS))[t] = __ldg(&p.b[L][t]);
        gemm_layer<8>(g, sb, 8192 + (L - 1) * 65536, 256, t, lane, wm, wn, acc);
        epilogue_A<8>(g, lane, wm, wn, acc);
    }

    // layer 8: 256 -> 257 (GEMM cols 1..256; col 0 = sigma scalar path)
    if (t < 256) {
        ((float*)(g + BIAS))[t]  = __ldg(&p.b[8][t + 1]);
        ((float*)(g + WCOL0))[t] = __ldg(&p.W[8][(size_t)t * 257]);
    }
    gemm_layer<8>(g, sb, 466944, 256, t, lane, wm, wn, acc);
    {   // sigma from A (layer-8 input, hi+lo) before epilogue overwrites A
        int r = t >> 2, q = t & 3;
        const float* wc = (const float*)(g + WCOL0);
        float s = 0.f;
#pragma unroll 4
        for (int k = q * 64; k < q * 64 + 64; k++) {
            float hv = __half2float(*(const __half*)(g + A_HI + r * SA_B + k * 2))
                     + __half2float(*(const __half*)(g + A_LO + r * SA_B + k * 2));
            s += hv * wc[k];
        }
        s += __shfl_xor_sync(0xffffffffu, s, 1);
        s += __shfl_xor_sync(0xffffffffu, s, 2);
        if (!q && (s0 + r) < ns) out[s0 + r] = fmaxf(s + __ldg(&p.b[8][0]), 0.f);
        __syncthreads();
    }
    epilogue_A<8>(g, lane, wm, wn, acc);       // fx -> A cols 0..255

    // stage d -> A cols 256..267, zero 268..271
    {
        int r = t >> 2, q = t & 3;
        const float* dr = p.d + (size_t)(s0 + r) * 12;
#pragma unroll
        for (int pr = 0; pr < 2; pr++) {
            int kg = 256 + q * 4 + pr * 2;
            float v0 = (kg     < 268) ? dr[kg - 256]     : 0.f;
            float v1 = (kg + 1 < 268) ? dr[kg + 1 - 256] : 0.f;
            uint32_t lo, hi = packsplit(v0, v1, lo);
            *(uint32_t*)(g + A_HI + r * SA_B + kg * 2) = hi;
            *(uint32_t*)(g + A_LO + r * SA_B + kg * 2) = lo;
        }
    }
    if (t < 128) ((float*)(g + BIAS))[t] = __ldg(&p.bc0[t]);
    if (t < 384) ((float*)(g + WC1O))[t] = __ldg(&p.Wc1[t]);
    __syncthreads();

    // color layer 0: 268 -> 128 (K padded to 272; 8 full chunks + one 16-k)
    gemm_layer<4>(g, sb, 532480, 272, t, lane, wm, wn, acc);
    epilogue_HC(g, lane, wm, wn, acc);

    // head: c = relu(hc @ Wc1 + bc1)
    if (t < 384) {
        int r = t / 3, j = t - r * 3;
        const float* hc  = (const float*)(g + HCOFF + r * SHC_B);
        const float* wc1 = (const float*)(g + WC1O);
        float s = 0.f;
#pragma unroll 4
        for (int k = 0; k < 128; k++) s += hc[k] * wc1[k * 3 + j];
        if ((s0 + r) < ns)
            out[(size_t)ns + (size_t)(s0 + r) * 3 + j] = fmaxf(s + __ldg(&p.bc1[j]), 0.f);
    }
}

extern "C" void kernel_launch(void* const* d_in, const int* in_sizes, int n_in,
                              void* d_out, int out_size) {
    Params p;
    p.x = (const float*)d_in[0];
    p.d = (const float*)d_in[1];
    for (int i = 0; i < 9; i++) {
        p.W[i] = (const float*)d_in[2 + 2 * i];
        p.b[i] = (const float*)d_in[3 + 2 * i];
    }
    p.Wc0 = (const float*)d_in[20];
    p.bc0 = (const float*)d_in[21];
    p.Wc1 = (const float*)d_in[22];
    p.bc1 = (const float*)d_in[23];

    int ns = in_sizes[0] / 30;   // 262144
    convert_weights<<<(BLOB_N + NT - 1) / NT, NT>>>(p);
    cudaFuncSetAttribute(nerf_hmma_kernel,
                         cudaFuncAttributeMaxDynamicSharedMemorySize, SMEM_SZ);
    int grid = (ns + 127) / 128; // 2048
    nerf_hmma_kernel<<<grid, NT, SMEM_SZ>>>(p, (float*)d_out, ns);
}

// round 8
// speedup vs baseline: 2.7844x; 1.1788x over previous
#include <cuda_runtime.h>
#include <cuda_fp16.h>
#include <cstdint>

// ---------------------------------------------------------------------------
// NeRF fused MLP via mma.sync m16n8k16 (f16 in, fp32 acc), hi/lo split:
// D = Ahi*Bhi + Alo*Bhi + Ahi*Blo.  128 samples/CTA, 512 threads, 4x4 warps.
// Weights pre-converted once into __device__ hi/lo blobs (per-chunk [n][k]).
// NEW: four decoupled warp-group pipelines — each group (4 warps, one per
// SMSP) stages only its own 64 W-columns and syncs with a 128-thread named
// barrier (1 per chunk); full-CTA barriers only around epilogues.
// ---------------------------------------------------------------------------

#define NT 512

// A: [128][280] halves, row stride 560 B (bank shift 12 -> conflict-free)
#define SA_B   560
#define A_HI   0
#define A_LO   71680
// W double buffer: per buffer {hi,lo}, each 256 n-rows x 80 B (64 data+16 pad)
#define W_BASE 143360
#define W_BUFB 40960            // byte stride between buffer 0 and 1
#define W_LOD  20480            // lo plane offset within a buffer
#define BIAS   225280
#define WCOL0  226304
#define WC1O   227328
#define SMEM_SZ 228864
// hc f32 [128][132] overlaid on W region (dead during head)
#define HCOFF  143360
#define SHC_B  528

// weight blob layout (halves, per plane):
//  L0   @ 0      : 256n x 32k (k>=30 zero)                 = 8192
//  L1-7 @ 8192+(L-1)*65536 : 8 chunks x (256n x 32k)       = 65536 each
//  L8   @ 466944 : cols 1..256 shifted                     = 65536
//  Wc0  @ 532480 : 8 chunks x (128n x 32k) + 1 x (128n x 16k), k>=268 zero
#define BLOB_N 567296
__device__ __half g_whi[BLOB_N];
__device__ __half g_wlo[BLOB_N];

struct Params {
    const float* x; const float* d;
    const float* W[9]; const float* b[9];
    const float* Wc0; const float* bc0;
    const float* Wc1; const float* bc1;
};

__device__ __forceinline__ void mma16816(float c[4], uint32_t a0, uint32_t a1,
                                         uint32_t a2, uint32_t a3,
                                         uint32_t b0, uint32_t b1) {
    asm("mma.sync.aligned.m16n8k16.row.col.f32.f16.f16.f32 "
        "{%0,%1,%2,%3}, {%4,%5,%6,%7}, {%8,%9}, {%0,%1,%2,%3};"
        : "+f"(c[0]), "+f"(c[1]), "+f"(c[2]), "+f"(c[3])
        : "r"(a0), "r"(a1), "r"(a2), "r"(a3), "r"(b0), "r"(b1));
}
__device__ __forceinline__ uint32_t pack2(__half a, __half b) {
    return (uint32_t)__half_as_ushort(a) | ((uint32_t)__half_as_ushort(b) << 16);
}
__device__ __forceinline__ void hsplit(float v, __half& h, __half& l) {
    h = __float2half_rn(v);
    l = __float2half_rn(v - __half2float(h));
}
__device__ __forceinline__ uint32_t packsplit(float v0, float v1, uint32_t& lo) {
    __half h0, l0, h1, l1;
    hsplit(v0, h0, l0); hsplit(v1, h1, l1);
    lo = pack2(l0, l1);
    return pack2(h0, h1);
}
#define CP_COMMIT() asm volatile("cp.async.commit_group;")
#define CP_WAIT0()  asm volatile("cp.async.wait_group 0;")
#define BAR_GRP(id) asm volatile("bar.sync %0, 128;" :: "r"(id) : "memory")

// ---- prologue: convert all weights f32 -> hi/lo f16 blobs ------------------
__global__ void convert_weights(Params p) {
    int idx = blockIdx.x * blockDim.x + threadIdx.x;
    if (idx >= BLOB_N) return;
    float v;
    if (idx < 8192) {                       // L0
        int n = idx >> 5, kk = idx & 31;
        v = (kk < 30) ? __ldg(&p.W[0][kk * 256 + n]) : 0.f;
    } else if (idx < 532480) {              // L1..L8
        int i = idx - 8192;
        int L = 1 + i / 65536;
        int r = i & 65535;
        int gk = (r >> 13) * 32 + (r & 31);
        int n  = (r >> 5) & 255;
        v = (L <= 7) ? __ldg(&p.W[L][(size_t)gk * 256 + n])
                     : __ldg(&p.W[8][(size_t)gk * 257 + n + 1]);
    } else {                                // Wc0
        int i = idx - 532480;
        if (i < 32768) {
            int gk = (i >> 12) * 32 + (i & 31);
            int n  = (i >> 5) & 127;
            v = __ldg(&p.Wc0[(size_t)gk * 128 + n]);
        } else {
            int j = i - 32768;
            int n = j >> 4, gk = 256 + (j & 15);
            v = (gk < 268) ? __ldg(&p.Wc0[(size_t)gk * 128 + n]) : 0.f;
        }
    }
    __half h, l; hsplit(v, h, l);
    g_whi[idx] = h; g_wlo[idx] = l;
}

// ---- stage this group's W-slice of one chunk (16B cp.async) ----------------
// rows [n0, n0+NG), kw halves per row (blob row stride = kw), csh: log2(kw/8)
__device__ __forceinline__ void stage_grp(uint32_t dstb, const __half* hs,
                                          const __half* ls, int n0, int NG,
                                          int kw, int csh, int tl) {
    int cpr = 1 << csh;                    // 16B copies per row per plane
    int total = NG * cpr;
#pragma unroll 1
    for (int idx = tl; idx < 2 * total; idx += 128) {
        int pl = (idx >= total) ? 1 : 0;
        int i  = idx - pl * total;
        int n  = n0 + (i >> csh);
        int j  = i & (cpr - 1);
        const __half* s = (pl ? ls : hs) + n * kw + j * 8;
        uint32_t dd = dstb + pl * W_LOD + n * 80 + j * 16;
        asm volatile("cp.async.cg.shared.global [%0], [%1], 16;"
                     :: "r"(dd), "l"(s));
    }
}

// ---- GEMM: acc = A[128 x K] @ W[K x NW]; per-group decoupled pipeline ------
template<int NTILES>
__device__ __forceinline__ void gemm_layer(char* g, uint32_t sb, int base,
                                           int K, int t, int lane, int wm,
                                           int wn, float acc[][4]) {
    constexpr int NW = NTILES * 32;
    constexpr int NG = NW / 4;             // this group's W-row count
#pragma unroll
    for (int i = 0; i < 2 * NTILES; i++)
#pragma unroll
        for (int j = 0; j < 4; j++) acc[i][j] = 0.f;

    const int g8 = lane >> 2, tig = lane & 3;
    const int tl = t & 127;
    const int bar_id = 1 + (t >> 7);       // 1 + wn
    const int n0 = wn * NG;
    const int nch = (K + 31) >> 5;

    {   // chunk 0
        int kw = min(32, K);
        stage_grp(sb + W_BASE, g_whi + base, g_wlo + base, n0, NG, kw,
                  (kw == 32) ? 2 : 1, tl);
        CP_COMMIT();
    }
#pragma unroll 1
    for (int c = 0; c < nch; c++) {
        CP_WAIT0();                        // chunk c data arrived (this thread)
        BAR_GRP(bar_id);                   // publish to group; also orders
                                           // group's chunk c-1 reads before the
                                           // restage below
        if (c + 1 < nch) {
            int kw2 = min(32, K - (c + 1) * 32);
            int off = base + NW * 32 * (c + 1);
            stage_grp(sb + W_BASE + ((c + 1) & 1) * W_BUFB,
                      g_whi + off, g_wlo + off, n0, NG, kw2,
                      (kw2 == 32) ? 2 : 1, tl);
            CP_COMMIT();                   // overlaps with MMA below
        }
        const char* wh = g + W_BASE + (c & 1) * W_BUFB;
        int ksteps = min(32, K - c * 32) >> 4;
#pragma unroll 1
        for (int ks = 0; ks < ksteps; ks++) {
            int kg = c * 32 + ks * 16;
            int kl = ks * 16;
            uint32_t ah[2][4], al[2][4];
#pragma unroll
            for (int mt = 0; mt < 2; mt++) {
                int r0 = wm * 32 + mt * 16 + g8;
                const char* ba = g + r0 * SA_B + (kg + tig * 2) * 2;
                ah[mt][0] = *(const uint32_t*)(ba + A_HI);
                ah[mt][1] = *(const uint32_t*)(ba + A_HI + 8 * SA_B);
                ah[mt][2] = *(const uint32_t*)(ba + A_HI + 16);
                ah[mt][3] = *(const uint32_t*)(ba + A_HI + 8 * SA_B + 16);
                al[mt][0] = *(const uint32_t*)(ba + A_LO);
                al[mt][1] = *(const uint32_t*)(ba + A_LO + 8 * SA_B);
                al[mt][2] = *(const uint32_t*)(ba + A_LO + 16);
                al[mt][3] = *(const uint32_t*)(ba + A_LO + 8 * SA_B + 16);
            }
#pragma unroll
            for (int nt = 0; nt < NTILES; nt++) {
                int nn = wn * (NTILES * 8) + nt * 8 + g8;
                const char* bw = wh + nn * 80 + (kl + tig * 2) * 2;
                uint32_t bh0 = *(const uint32_t*)(bw);
                uint32_t bh1 = *(const uint32_t*)(bw + 16);
                uint32_t bl0 = *(const uint32_t*)(bw + W_LOD);
                uint32_t bl1 = *(const uint32_t*)(bw + W_LOD + 16);
#pragma unroll
                for (int mt = 0; mt < 2; mt++) {
                    mma16816(acc[mt * NTILES + nt], ah[mt][0], ah[mt][1], ah[mt][2], ah[mt][3], bh0, bh1);
                    mma16816(acc[mt * NTILES + nt], al[mt][0], al[mt][1], al[mt][2], al[mt][3], bh0, bh1);
                    mma16816(acc[mt * NTILES + nt], ah[mt][0], ah[mt][1], ah[mt][2], ah[mt][3], bl0, bl1);
                }
            }
        }
    }
}

// ---- epilogue: bias + ReLU, hi/lo split back into A ------------------------
template<int NTILES>
__device__ __forceinline__ void epilogue_A(char* g, int lane, int wm, int wn,
                                           float acc[][4]) {
    __syncthreads();                       // all groups' A reads done
    const int g8 = lane >> 2, tig = lane & 3;
    const float* bias = (const float*)(g + BIAS);
#pragma unroll
    for (int mt = 0; mt < 2; mt++) {
#pragma unroll
        for (int nt = 0; nt < NTILES; nt++) {
            int r1 = wm * 32 + mt * 16 + g8, r2 = r1 + 8;
            int cb = wn * (NTILES * 8) + nt * 8 + tig * 2;
            float* a = acc[mt * NTILES + nt];
            float b0 = bias[cb], b1 = bias[cb + 1];
            uint32_t lo, hi;
            hi = packsplit(fmaxf(a[0] + b0, 0.f), fmaxf(a[1] + b1, 0.f), lo);
            *(uint32_t*)(g + A_HI + r1 * SA_B + cb * 2) = hi;
            *(uint32_t*)(g + A_LO + r1 * SA_B + cb * 2) = lo;
            hi = packsplit(fmaxf(a[2] + b0, 0.f), fmaxf(a[3] + b1, 0.f), lo);
            *(uint32_t*)(g + A_HI + r2 * SA_B + cb * 2) = hi;
            *(uint32_t*)(g + A_LO + r2 * SA_B + cb * 2) = lo;
        }
    }
    __syncthreads();
}

// color epilogue: bias + ReLU -> hc f32 (overlaid on W region)
__device__ __forceinline__ void epilogue_HC(char* g, int lane, int wm, int wn,
                                            float acc[][4]) {
    __syncthreads();                       // all groups' A/W reads done
    const int g8 = lane >> 2, tig = lane & 3;
    const float* bias = (const float*)(g + BIAS);
#pragma unroll
    for (int mt = 0; mt < 2; mt++) {
#pragma unroll
        for (int nt = 0; nt < 4; nt++) {
            int r1 = wm * 32 + mt * 16 + g8, r2 = r1 + 8;
            int cb = wn * 32 + nt * 8 + tig * 2;
            float* a = acc[mt * 4 + nt];
            float b0 = bias[cb], b1 = bias[cb + 1];
            float2 v1 = make_float2(fmaxf(a[0] + b0, 0.f), fmaxf(a[1] + b1, 0.f));
            float2 v2 = make_float2(fmaxf(a[2] + b0, 0.f), fmaxf(a[3] + b1, 0.f));
            *(float2*)(g + HCOFF + r1 * SHC_B + cb * 4) = v1;
            *(float2*)(g + HCOFF + r2 * SHC_B + cb * 4) = v2;
        }
    }
    __syncthreads();
}

// ---- main kernel -----------------------------------------------------------
__global__ void __launch_bounds__(NT, 1)
nerf_hmma_kernel(Params p, float* __restrict__ out, int ns) {
    extern __shared__ char g[];
    uint32_t sb = (uint32_t)__cvta_generic_to_shared(g);
    int t = threadIdx.x, lane = t & 31, w = t >> 5;
    int wm = w & 3, wn = w >> 2;
    int s0 = blockIdx.x * 128;
    float acc[16][4];

    // stage x -> A cols 0..31 (k>=30 zero)
    {
        int r = t >> 2, q = t & 3;
        const float* xr = p.x + (size_t)(s0 + r) * 30;
#pragma unroll
        for (int pr = 0; pr < 4; pr++) {
            int k = q * 8 + pr * 2;
            float v0 = (k     < 30) ? xr[k]     : 0.f;
            float v1 = (k + 1 < 30) ? xr[k + 1] : 0.f;
            uint32_t lo, hi = packsplit(v0, v1, lo);
            *(uint32_t*)(g + A_HI + r * SA_B + k * 2) = hi;
            *(uint32_t*)(g + A_LO + r * SA_B + k * 2) = lo;
        }
    }
    if (t < 256) ((float*)(g + BIAS))[t] = __ldg(&p.b[0][t]);
    __syncthreads();

    // layer 0: 30 -> 256
    gemm_layer<8>(g, sb, 0, 32, t, lane, wm, wn, acc);
    epilogue_A<8>(g, lane, wm, wn, acc);

    // layers 1..7: 256 -> 256
#pragma unroll 1
    for (int L = 1; L <= 7; L++) {
        if (t < 256) ((float*)(g + BIAS))[t] = __ldg(&p.b[L][t]);
        gemm_layer<8>(g, sb, 8192 + (L - 1) * 65536, 256, t, lane, wm, wn, acc);
        epilogue_A<8>(g, lane, wm, wn, acc);
    }

    // layer 8: 256 -> 257 (GEMM cols 1..256; col 0 = sigma scalar path)
    if (t < 256) {
        ((float*)(g + BIAS))[t]  = __ldg(&p.b[8][t + 1]);
        ((float*)(g + WCOL0))[t] = __ldg(&p.W[8][(size_t)t * 257]);
    }
    gemm_layer<8>(g, sb, 466944, 256, t, lane, wm, wn, acc);
    {   // sigma from A (layer-8 input, hi+lo) before epilogue overwrites A
        __syncthreads();                   // all groups done; WCOL0 visible
        int r = t >> 2, q = t & 3;
        const float* wc = (const float*)(g + WCOL0);
        float s = 0.f;
#pragma unroll 4
        for (int k = q * 64; k < q * 64 + 64; k++) {
            float hv = __half2float(*(const __half*)(g + A_HI + r * SA_B + k * 2))
                     + __half2float(*(const __half*)(g + A_LO + r * SA_B + k * 2));
            s += hv * wc[k];
        }
        s += __shfl_xor_sync(0xffffffffu, s, 1);
        s += __shfl_xor_sync(0xffffffffu, s, 2);
        if (!q && (s0 + r) < ns) out[s0 + r] = fmaxf(s + __ldg(&p.b[8][0]), 0.f);
    }
    epilogue_A<8>(g, lane, wm, wn, acc);   // fx -> A cols 0..255

    // stage d -> A cols 256..267, zero 268..271
    {
        int r = t >> 2, q = t & 3;
        const float* dr = p.d + (size_t)(s0 + r) * 12;
#pragma unroll
        for (int pr = 0; pr < 2; pr++) {
            int kg = 256 + q * 4 + pr * 2;
            float v0 = (kg     < 268) ? dr[kg - 256]     : 0.f;
            float v1 = (kg + 1 < 268) ? dr[kg + 1 - 256] : 0.f;
            uint32_t lo, hi = packsplit(v0, v1, lo);
            *(uint32_t*)(g + A_HI + r * SA_B + kg * 2) = hi;
            *(uint32_t*)(g + A_LO + r * SA_B + kg * 2) = lo;
        }
    }
    if (t < 128) ((float*)(g + BIAS))[t] = __ldg(&p.bc0[t]);
    if (t < 384) ((float*)(g + WC1O))[t] = __ldg(&p.Wc1[t]);
    __syncthreads();

    // color layer 0: 268 -> 128 (K padded to 272; 8 full chunks + one 16-k)
    gemm_layer<4>(g, sb, 532480, 272, t, lane, wm, wn, acc);
    epilogue_HC(g, lane, wm, wn, acc);

    // head: c = relu(hc @ Wc1 + bc1)
    if (t < 384) {
        int r = t / 3, j = t - r * 3;
        const float* hc  = (const float*)(g + HCOFF + r * SHC_B);
        const float* wc1 = (const float*)(g + WC1O);
        float s = 0.f;
#pragma unroll 4
        for (int k = 0; k < 128; k++) s += hc[k] * wc1[k * 3 + j];
        if ((s0 + r) < ns)
            out[(size_t)ns + (size_t)(s0 + r) * 3 + j] = fmaxf(s + __ldg(&p.bc1[j]), 0.f);
    }
}

extern "C" void kernel_launch(void* const* d_in, const int* in_sizes, int n_in,
                              void* d_out, int out_size) {
    Params p;
    p.x = (const float*)d_in[0];
    p.d = (const float*)d_in[1];
    for (int i = 0; i < 9; i++) {
        p.W[i] = (const float*)d_in[2 + 2 * i];
        p.b[i] = (const float*)d_in[3 + 2 * i];
    }
    p.Wc0 = (const float*)d_in[20];
    p.bc0 = (const float*)d_in[21];
    p.Wc1 = (const float*)d_in[22];
    p.bc1 = (const float*)d_in[23];

    int ns = in_sizes[0] / 30;   // 262144
    convert_weights<<<(BLOB_N + NT - 1) / NT, NT>>>(p);
    cudaFuncSetAttribute(nerf_hmma_kernel,
                         cudaFuncAttributeMaxDynamicSharedMemorySize, SMEM_SZ);
    int grid = (ns + 127) / 128; // 2048
    nerf_hmma_kernel<<<grid, NT, SMEM_SZ>>>(p, (float*)d_out, ns);
}

// round 9
// speedup vs baseline: 2.8833x; 1.0355x over previous
#include <cuda_runtime.h>
#include <cuda_fp16.h>
#include <cstdint>

// ---------------------------------------------------------------------------
// NeRF fused MLP via mma.sync m16n8k16 (f16 in, fp32 acc), hi/lo split:
// D = Ahi*Bhi + Alo*Bhi + Ahi*Blo.  128 samples/CTA, 512 threads, 4x4 warps.
// Weights pre-converted once into __device__ hi/lo blobs (per-chunk [n][k]);
// per-warp-group decoupled pipelines with named barriers (R8).
// NEW (R9): ldmatrix.x4 fragment loads (12 LDSM/ks vs 48 LDS.32) and
// explicitly unrolled k-steps so LDSM latency hides under the MMA chain.
// ---------------------------------------------------------------------------

#define NT 512

// A: [128][280] halves, row stride 560 B (bank shift 12 -> conflict-free)
#define SA_B   560
#define A_HI   0
#define A_LO   71680
// W double buffer: per buffer {hi,lo}, each 256 n-rows x 80 B (64 data+16 pad)
#define W_BASE 143360
#define W_BUFB 40960            // byte stride between buffer 0 and 1
#define W_LOD  20480            // lo plane offset within a buffer
#define BIAS   225280
#define WCOL0  226304
#define WC1O   227328
#define SMEM_SZ 228864
// hc f32 [128][132] overlaid on W region (dead during head)
#define HCOFF  143360
#define SHC_B  528

// weight blob layout (halves, per plane):
//  L0   @ 0      : 256n x 32k (k>=30 zero)                 = 8192
//  L1-7 @ 8192+(L-1)*65536 : 8 chunks x (256n x 32k)       = 65536 each
//  L8   @ 466944 : cols 1..256 shifted                     = 65536
//  Wc0  @ 532480 : 8 chunks x (128n x 32k) + 1 x (128n x 16k), k>=268 zero
#define BLOB_N 567296
__device__ __half g_whi[BLOB_N];
__device__ __half g_wlo[BLOB_N];

struct Params {
    const float* x; const float* d;
    const float* W[9]; const float* b[9];
    const float* Wc0; const float* bc0;
    const float* Wc1; const float* bc1;
};

__device__ __forceinline__ void mma16816(float c[4], uint32_t a0, uint32_t a1,
                                         uint32_t a2, uint32_t a3,
                                         uint32_t b0, uint32_t b1) {
    asm("mma.sync.aligned.m16n8k16.row.col.f32.f16.f16.f32 "
        "{%0,%1,%2,%3}, {%4,%5,%6,%7}, {%8,%9}, {%0,%1,%2,%3};"
        : "+f"(c[0]), "+f"(c[1]), "+f"(c[2]), "+f"(c[3])
        : "r"(a0), "r"(a1), "r"(a2), "r"(a3), "r"(b0), "r"(b1));
}
__device__ __forceinline__ void ldsm4(uint32_t r[4], uint32_t addr) {
    asm volatile("ldmatrix.sync.aligned.m8n8.x4.shared.b16 {%0,%1,%2,%3}, [%4];"
                 : "=r"(r[0]), "=r"(r[1]), "=r"(r[2]), "=r"(r[3]) : "r"(addr));
}
__device__ __forceinline__ uint32_t pack2(__half a, __half b) {
    return (uint32_t)__half_as_ushort(a) | ((uint32_t)__half_as_ushort(b) << 16);
}
__device__ __forceinline__ void hsplit(float v, __half& h, __half& l) {
    h = __float2half_rn(v);
    l = __float2half_rn(v - __half2float(h));
}
__device__ __forceinline__ uint32_t packsplit(float v0, float v1, uint32_t& lo) {
    __half h0, l0, h1, l1;
    hsplit(v0, h0, l0); hsplit(v1, h1, l1);
    lo = pack2(l0, l1);
    return pack2(h0, h1);
}
#define CP_COMMIT() asm volatile("cp.async.commit_group;")
#define CP_WAIT0()  asm volatile("cp.async.wait_group 0;")
#define BAR_GRP(id) asm volatile("bar.sync %0, 128;" :: "r"(id) : "memory")

// ---- prologue: convert all weights f32 -> hi/lo f16 blobs ------------------
__global__ void convert_weights(Params p) {
    int idx = blockIdx.x * blockDim.x + threadIdx.x;
    if (idx >= BLOB_N) return;
    float v;
    if (idx < 8192) {                       // L0
        int n = idx >> 5, kk = idx & 31;
        v = (kk < 30) ? __ldg(&p.W[0][kk * 256 + n]) : 0.f;
    } else if (idx < 532480) {              // L1..L8
        int i = idx - 8192;
        int L = 1 + i / 65536;
        int r = i & 65535;
        int gk = (r >> 13) * 32 + (r & 31);
        int n  = (r >> 5) & 255;
        v = (L <= 7) ? __ldg(&p.W[L][(size_t)gk * 256 + n])
                     : __ldg(&p.W[8][(size_t)gk * 257 + n + 1]);
    } else {                                // Wc0
        int i = idx - 532480;
        if (i < 32768) {
            int gk = (i >> 12) * 32 + (i & 31);
            int n  = (i >> 5) & 127;
            v = __ldg(&p.Wc0[(size_t)gk * 128 + n]);
        } else {
            int j = i - 32768;
            int n = j >> 4, gk = 256 + (j & 15);
            v = (gk < 268) ? __ldg(&p.Wc0[(size_t)gk * 128 + n]) : 0.f;
        }
    }
    __half h, l; hsplit(v, h, l);
    g_whi[idx] = h; g_wlo[idx] = l;
}

// ---- stage this group's W-slice of one chunk (16B cp.async) ----------------
__device__ __forceinline__ void stage_grp(uint32_t dstb, const __half* hs,
                                          const __half* ls, int n0, int NG,
                                          int kw, int csh, int tl) {
    int cpr = 1 << csh;                    // 16B copies per row per plane
    int total = NG * cpr;
#pragma unroll 1
    for (int idx = tl; idx < 2 * total; idx += 128) {
        int pl = (idx >= total) ? 1 : 0;
        int i  = idx - pl * total;
        int n  = n0 + (i >> csh);
        int j  = i & (cpr - 1);
        const __half* s = (pl ? ls : hs) + n * kw + j * 8;
        uint32_t dd = dstb + pl * W_LOD + n * 80 + j * 16;
        asm volatile("cp.async.cg.shared.global [%0], [%1], 16;"
                     :: "r"(dd), "l"(s));
    }
}

// ---- GEMM: acc = A[128 x K] @ W[K x NW]; decoupled groups + ldmatrix -------
template<int NTILES>
__device__ __forceinline__ void gemm_layer(char* g, uint32_t sb, int base,
                                           int K, int t, int lane, int wm,
                                           int wn, float acc[][4]) {
    constexpr int NW = NTILES * 32;
    constexpr int NG = NW / 4;             // this group's W-row count
#pragma unroll
    for (int i = 0; i < 2 * NTILES; i++)
#pragma unroll
        for (int j = 0; j < 4; j++) acc[i][j] = 0.f;

    const int tl = t & 127;
    const int bar_id = 1 + (t >> 7);       // 1 + wn
    const int n0 = wn * NG;
    const int nch = (K + 31) >> 5;

    // ldmatrix lane bases
    // A: row = wm*32 + mt*16 + (lane&15); 16B col offset = (lane>>4)*16
    const uint32_t a_base = sb + A_HI + (uint32_t)(wm * 32 + (lane & 15)) * SA_B
                          + (uint32_t)(lane >> 4) * 16;
    // B: q = lane>>3: n_loc = (lane&7) + (q>>1)*8, k 16B offset = (q&1)*16
    const int q = lane >> 3;
    const uint32_t b_lane = (uint32_t)(((lane & 7) + ((q >> 1) << 3)) * 80
                                       + (q & 1) * 16);

    {   // chunk 0
        int kw = min(32, K);
        stage_grp(sb + W_BASE, g_whi + base, g_wlo + base, n0, NG, kw,
                  (kw == 32) ? 2 : 1, tl);
        CP_COMMIT();
    }

    auto do_ks = [&](uint32_t wb, int kg, int kl) {
        uint32_t ah[2][4], al[2][4];
        ldsm4(ah[0], a_base + (uint32_t)kg * 2);
        ldsm4(ah[1], a_base + 16 * SA_B + (uint32_t)kg * 2);
        ldsm4(al[0], a_base + (A_LO - A_HI) + (uint32_t)kg * 2);
        ldsm4(al[1], a_base + (A_LO - A_HI) + 16 * SA_B + (uint32_t)kg * 2);
#pragma unroll
        for (int ntp = 0; ntp < NTILES / 2; ntp++) {
            uint32_t bb = wb + (uint32_t)((wn * (NTILES * 8) + ntp * 16) * 80)
                        + b_lane + (uint32_t)kl * 2;
            uint32_t bh[4], bl[4];
            ldsm4(bh, bb);
            ldsm4(bl, bb + W_LOD);
#pragma unroll
            for (int sub = 0; sub < 2; sub++) {
#pragma unroll
                for (int mt = 0; mt < 2; mt++) {
                    float* a = acc[mt * NTILES + 2 * ntp + sub];
                    mma16816(a, ah[mt][0], ah[mt][1], ah[mt][2], ah[mt][3],
                             bh[2 * sub], bh[2 * sub + 1]);
                    mma16816(a, al[mt][0], al[mt][1], al[mt][2], al[mt][3],
                             bh[2 * sub], bh[2 * sub + 1]);
                    mma16816(a, ah[mt][0], ah[mt][1], ah[mt][2], ah[mt][3],
                             bl[2 * sub], bl[2 * sub + 1]);
                }
            }
        }
    };

#pragma unroll 1
    for (int c = 0; c < nch; c++) {
        CP_WAIT0();                        // chunk c data arrived (this thread)
        BAR_GRP(bar_id);                   // publish to group; orders group's
                                           // chunk c-1 reads before restage
        if (c + 1 < nch) {
            int kw2 = min(32, K - (c + 1) * 32);
            int off = base + NW * 32 * (c + 1);
            stage_grp(sb + W_BASE + ((c + 1) & 1) * W_BUFB,
                      g_whi + off, g_wlo + off, n0, NG, kw2,
                      (kw2 == 32) ? 2 : 1, tl);
            CP_COMMIT();                   // overlaps with MMA below
        }
        uint32_t wb = sb + W_BASE + (uint32_t)((c & 1) * W_BUFB);
        int ksteps = min(32, K - c * 32) >> 4;
        do_ks(wb, c * 32, 0);
        if (ksteps == 2) do_ks(wb, c * 32 + 16, 16);
    }
}

// ---- epilogue: bias + ReLU, hi/lo split back into A ------------------------
template<int NTILES>
__device__ __forceinline__ void epilogue_A(char* g, int lane, int wm, int wn,
                                           float acc[][4]) {
    __syncthreads();                       // all groups' A reads done
    const int g8 = lane >> 2, tig = lane & 3;
    const float* bias = (const float*)(g + BIAS);
#pragma unroll
    for (int mt = 0; mt < 2; mt++) {
#pragma unroll
        for (int nt = 0; nt < NTILES; nt++) {
            int r1 = wm * 32 + mt * 16 + g8, r2 = r1 + 8;
            int cb = wn * (NTILES * 8) + nt * 8 + tig * 2;
            float* a = acc[mt * NTILES + nt];
            float b0 = bias[cb], b1 = bias[cb + 1];
            uint32_t lo, hi;
            hi = packsplit(fmaxf(a[0] + b0, 0.f), fmaxf(a[1] + b1, 0.f), lo);
            *(uint32_t*)(g + A_HI + r1 * SA_B + cb * 2) = hi;
            *(uint32_t*)(g + A_LO + r1 * SA_B + cb * 2) = lo;
            hi = packsplit(fmaxf(a[2] + b0, 0.f), fmaxf(a[3] + b1, 0.f), lo);
            *(uint32_t*)(g + A_HI + r2 * SA_B + cb * 2) = hi;
            *(uint32_t*)(g + A_LO + r2 * SA_B + cb * 2) = lo;
        }
    }
    __syncthreads();
}

// color epilogue: bias + ReLU -> hc f32 (overlaid on W region)
__device__ __forceinline__ void epilogue_HC(char* g, int lane, int wm, int wn,
                                            float acc[][4]) {
    __syncthreads();                       // all groups' A/W reads done
    const int g8 = lane >> 2, tig = lane & 3;
    const float* bias = (const float*)(g + BIAS);
#pragma unroll
    for (int mt = 0; mt < 2; mt++) {
#pragma unroll
        for (int nt = 0; nt < 4; nt++) {
            int r1 = wm * 32 + mt * 16 + g8, r2 = r1 + 8;
            int cb = wn * 32 + nt * 8 + tig * 2;
            float* a = acc[mt * 4 + nt];
            float b0 = bias[cb], b1 = bias[cb + 1];
            float2 v1 = make_float2(fmaxf(a[0] + b0, 0.f), fmaxf(a[1] + b1, 0.f));
            float2 v2 = make_float2(fmaxf(a[2] + b0, 0.f), fmaxf(a[3] + b1, 0.f));
            *(float2*)(g + HCOFF + r1 * SHC_B + cb * 4) = v1;
            *(float2*)(g + HCOFF + r2 * SHC_B + cb * 4) = v2;
        }
    }
    __syncthreads();
}

// ---- main kernel -----------------------------------------------------------
__global__ void __launch_bounds__(NT, 1)
nerf_hmma_kernel(Params p, float* __restrict__ out, int ns) {
    extern __shared__ char g[];
    uint32_t sb = (uint32_t)__cvta_generic_to_shared(g);
    int t = threadIdx.x, lane = t & 31, w = t >> 5;
    int wm = w & 3, wn = w >> 2;
    int s0 = blockIdx.x * 128;
    float acc[16][4];

    // stage x -> A cols 0..31 (k>=30 zero)
    {
        int r = t >> 2, q = t & 3;
        const float* xr = p.x + (size_t)(s0 + r) * 30;
#pragma unroll
        for (int pr = 0; pr < 4; pr++) {
            int k = q * 8 + pr * 2;
            float v0 = (k     < 30) ? xr[k]     : 0.f;
            float v1 = (k + 1 < 30) ? xr[k + 1] : 0.f;
            uint32_t lo, hi = packsplit(v0, v1, lo);
            *(uint32_t*)(g + A_HI + r * SA_B + k * 2) = hi;
            *(uint32_t*)(g + A_LO + r * SA_B + k * 2) = lo;
        }
    }
    if (t < 256) ((float*)(g + BIAS))[t] = __ldg(&p.b[0][t]);
    __syncthreads();

    // layer 0: 30 -> 256
    gemm_layer<8>(g, sb, 0, 32, t, lane, wm, wn, acc);
    epilogue_A<8>(g, lane, wm, wn, acc);

    // layers 1..7: 256 -> 256
#pragma unroll 1
    for (int L = 1; L <= 7; L++) {
        if (t < 256) ((float*)(g + BIAS))[t] = __ldg(&p.b[L][t]);
        gemm_layer<8>(g, sb, 8192 + (L - 1) * 65536, 256, t, lane, wm, wn, acc);
        epilogue_A<8>(g, lane, wm, wn, acc);
    }

    // layer 8: 256 -> 257 (GEMM cols 1..256; col 0 = sigma scalar path)
    if (t < 256) {
        ((float*)(g + BIAS))[t]  = __ldg(&p.b[8][t + 1]);
        ((float*)(g + WCOL0))[t] = __ldg(&p.W[8][(size_t)t * 257]);
    }
    gemm_layer<8>(g, sb, 466944, 256, t, lane, wm, wn, acc);
    {   // sigma from A (layer-8 input, hi+lo) before epilogue overwrites A
        __syncthreads();                   // all groups done; WCOL0 visible
        int r = t >> 2, q = t & 3;
        const float* wc = (const float*)(g + WCOL0);
        float s = 0.f;
#pragma unroll 4
        for (int k = q * 64; k < q * 64 + 64; k++) {
            float hv = __half2float(*(const __half*)(g + A_HI + r * SA_B + k * 2))
                     + __half2float(*(const __half*)(g + A_LO + r * SA_B + k * 2));
            s += hv * wc[k];
        }
        s += __shfl_xor_sync(0xffffffffu, s, 1);
        s += __shfl_xor_sync(0xffffffffu, s, 2);
        if (!q && (s0 + r) < ns) out[s0 + r] = fmaxf(s + __ldg(&p.b[8][0]), 0.f);
    }
    epilogue_A<8>(g, lane, wm, wn, acc);   // fx -> A cols 0..255

    // stage d -> A cols 256..267, zero 268..271
    {
        int r = t >> 2, q = t & 3;
        const float* dr = p.d + (size_t)(s0 + r) * 12;
#pragma unroll
        for (int pr = 0; pr < 2; pr++) {
            int kg = 256 + q * 4 + pr * 2;
            float v0 = (kg     < 268) ? dr[kg - 256]     : 0.f;
            float v1 = (kg + 1 < 268) ? dr[kg + 1 - 256] : 0.f;
            uint32_t lo, hi = packsplit(v0, v1, lo);
            *(uint32_t*)(g + A_HI + r * SA_B + kg * 2) = hi;
            *(uint32_t*)(g + A_LO + r * SA_B + kg * 2) = lo;
        }
    }
    if (t < 128) ((float*)(g + BIAS))[t] = __ldg(&p.bc0[t]);
    if (t < 384) ((float*)(g + WC1O))[t] = __ldg(&p.Wc1[t]);
    __syncthreads();

    // color layer 0: 268 -> 128 (K padded to 272; 8 full chunks + one 16-k)
    gemm_layer<4>(g, sb, 532480, 272, t, lane, wm, wn, acc);
    epilogue_HC(g, lane, wm, wn, acc);

    // head: c = relu(hc @ Wc1 + bc1)
    if (t < 384) {
        int r = t / 3, j = t - r * 3;
        const float* hc  = (const float*)(g + HCOFF + r * SHC_B);
        const float* wc1 = (const float*)(g + WC1O);
        float s = 0.f;
#pragma unroll 4
        for (int k = 0; k < 128; k++) s += hc[k] * wc1[k * 3 + j];
        if ((s0 + r) < ns)
            out[(size_t)ns + (size_t)(s0 + r) * 3 + j] = fmaxf(s + __ldg(&p.bc1[j]), 0.f);
    }
}

extern "C" void kernel_launch(void* const* d_in, const int* in_sizes, int n_in,
                              void* d_out, int out_size) {
    Params p;
    p.x = (const float*)d_in[0];
    p.d = (const float*)d_in[1];
    for (int i = 0; i < 9; i++) {
        p.W[i] = (const float*)d_in[2 + 2 * i];
        p.b[i] = (const float*)d_in[3 + 2 * i];
    }
    p.Wc0 = (const float*)d_in[20];
    p.bc0 = (const float*)d_in[21];
    p.Wc1 = (const float*)d_in[22];
    p.bc1 = (const float*)d_in[23];

    int ns = in_sizes[0] / 30;   // 262144
    convert_weights<<<(BLOB_N + NT - 1) / NT, NT>>>(p);
    cudaFuncSetAttribute(nerf_hmma_kernel,
                         cudaFuncAttributeMaxDynamicSharedMemorySize, SMEM_SZ);
    int grid = (ns + 127) / 128; // 2048
    nerf_hmma_kernel<<<grid, NT, SMEM_SZ>>>(p, (float*)d_out, ns);
}